// round 15
// baseline (speedup 1.0000x reference)
#include <cuda_runtime.h>
#include <cuda_bf16.h>
#include <cstdint>
#include <math.h>

#define MAXN 500000
#define MAXV 50000

// ---- scratch (static __device__ arrays; allocation-free) ----
__device__ __align__(128) __nv_bfloat16 g_pf2b[(size_t)MAXN * 128];   // pf2 bf16
__device__ __align__(128) float g_vox[(size_t)MAXV * 128];
__device__ __align__(128) __nv_bfloat16 g_voxfb[(size_t)MAXV * 128];  // voxf bf16
__device__ __align__(128) float g_voxh[(size_t)MAXV * 256];           // voxf @ w3_top
__device__ __align__(128) float g_vox2[(size_t)MAXV * 256];
__device__ __align__(128) __nv_bfloat16 g_w3top[40960];  // w3 rows 0..127  [4][256][40]
__device__ __align__(128) __nv_bfloat16 g_w3bot[40960];  // w3 rows 128..255
__device__ __align__(128) __nv_bfloat16 g_w4b[81920];    // w4 [8][256][40]
__device__ __align__(128) __nv_bfloat16 g_wvb[81920];    // wv2
__device__ __align__(128) __nv_bfloat16 g_wv1b[20480];   // wv1 [4][128][40]

__device__ __forceinline__ void amax_pos(float* addr, float v) {
    if (v > 0.f) atomicMax((int*)addr, __float_as_int(v));
}

__device__ __forceinline__ uint32_t f2tf32(float f) {
    uint32_t r;
    asm("cvt.rna.tf32.f32 %0, %1;" : "=r"(r) : "f"(f));
    return r;
}
__device__ __forceinline__ float tf32f(float f) { return __uint_as_float(f2tf32(f)); }

__device__ __forceinline__ uint32_t pack_bf16(float a, float b) {
    __nv_bfloat162 h = __floats2bfloat162_rn(a, b);
    uint32_t r;
    memcpy(&r, &h, 4);
    return r;
}

__device__ __forceinline__ uint32_t smem_u32(const void* p) {
    return (uint32_t)__cvta_generic_to_shared(p);
}
__device__ __forceinline__ void cp_async16(uint32_t dst, const void* src) {
    asm volatile("cp.async.cg.shared.global [%0], [%1], 16;" :: "r"(dst), "l"(src));
}
#define CP_COMMIT() asm volatile("cp.async.commit_group;" ::: "memory")
#define CP_WAIT0()  asm volatile("cp.async.wait_group 0;" ::: "memory")

__device__ __forceinline__ void ldsm4(uint32_t& r0, uint32_t& r1, uint32_t& r2,
                                      uint32_t& r3, uint32_t addr) {
    asm volatile("ldmatrix.sync.aligned.m8n8.x4.shared.b16 {%0,%1,%2,%3}, [%4];"
                 : "=r"(r0), "=r"(r1), "=r"(r2), "=r"(r3) : "r"(addr));
}

__device__ __forceinline__ void mma_bf16(float acc[4], uint32_t a0, uint32_t a1,
                                         uint32_t a2, uint32_t a3, uint32_t b0, uint32_t b1) {
    asm volatile(
        "mma.sync.aligned.m16n8k16.row.col.f32.bf16.bf16.f32 "
        "{%0,%1,%2,%3},{%4,%5,%6,%7},{%8,%9},{%0,%1,%2,%3};"
        : "+f"(acc[0]), "+f"(acc[1]), "+f"(acc[2]), "+f"(acc[3])
        : "r"(a0), "r"(a1), "r"(a2), "r"(a3), "r"(b0), "r"(b1));
}

__device__ __forceinline__ void mma_tf32(float acc[4], uint32_t a0, uint32_t a1,
                                         uint32_t a2, uint32_t a3, uint32_t b0, uint32_t b1) {
    asm volatile(
        "mma.sync.aligned.m16n8k8.row.col.f32.tf32.tf32.f32 "
        "{%0,%1,%2,%3},{%4,%5,%6,%7},{%8,%9},{%0,%1,%2,%3};"
        : "+f"(acc[0]), "+f"(acc[1]), "+f"(acc[2]), "+f"(acc[3])
        : "r"(a0), "r"(a1), "r"(a2), "r"(a3), "r"(b0), "r"(b1));
}

// k-pair permutation: within each 8-wide k block, place k at 2*(k&3) + ((k>>2)&1)
// so fragment pairs (k, k+4) are adjacent (enables LDS.64).
__device__ __forceinline__ int kperm(int k) {
    return (k & ~7) + 2 * (k & 3) + ((k >> 2) & 1);
}

// ---------------------------------------------------------------------------
__global__ void zero_k(int na, int nb) {
    int i = blockIdx.x * blockDim.x + threadIdx.x;
    int stride = gridDim.x * blockDim.x;
    for (int j = i; j < nb; j += stride) {
        if (j < na) g_vox[j] = 0.f;
        g_vox2[j] = 0.f;
    }
}

// blocked bf16 weight images: w [k][NCOL] row-major -> [kc][NCOL][40]
__device__ __forceinline__ void blk_one(const float* __restrict__ w,
                                        __nv_bfloat16* __restrict__ d, int j, int NCOL) {
    int per = NCOL * 40;
    int kc = j / per, rem = j % per, nn = rem / 40, kl = rem % 40;
    float v = (kl < 32) ? w[(size_t)(kc * 32 + kl) * NCOL + nn] : 0.f;
    d[j] = __float2bfloat16(v);
}

__global__ void prep_all(const float* __restrict__ w3, const float* __restrict__ w4,
                         const float* __restrict__ wv2, const float* __restrict__ wv1) {
    int i = blockIdx.x * blockDim.x + threadIdx.x;
    if (i < 40960) blk_one(w3, g_w3top, i, 256);
    else if (i < 81920) blk_one(w3 + 128 * 256, g_w3bot, i - 40960, 256);
    else if (i < 163840) blk_one(w4, g_w4b, i - 81920, 256);
    else if (i < 245760) blk_one(wv2, g_wvb, i - 163840, 256);
    else if (i < 266240) blk_one(wv1, g_wv1b, i - 245760, 128);
}

// ---------------------------------------------------------------------------
// Stage A via mma.sync tf32 — paired k layouts (LDS.64), fused attention pair.
// smem floats: sW 512 | sB 4x2560 | sA [128][68] | svx 128  (78 KB, 2 CTA/SM)
// B image layout: [k8][t4][col][2]: off = k8*320 + t4*80 + col*2 + j,
//   holds B[k8*8+t4+4j][col].
// ---------------------------------------------------------------------------
#define SAM_THREADS 256
#define SAM_SMEM ((512 + 10240 + 128 * 68 + 128) * 4)

__device__ __forceinline__ void gemmA_p(const float* __restrict__ As,
                                        const float* __restrict__ Bt,
                                        int wr, int g, int t4, float acc[4][4]) {
#pragma unroll
    for (int k8 = 0; k8 < 8; k8++) {
        float2 vlo = *(const float2*)(As + (wr + g) * 68 + k8 * 8 + 2 * t4);
        float2 vhi = *(const float2*)(As + (wr + g + 8) * 68 + k8 * 8 + 2 * t4);
        uint32_t a0 = __float_as_uint(vlo.x), a1 = __float_as_uint(vhi.x);
        uint32_t a2 = __float_as_uint(vlo.y), a3 = __float_as_uint(vhi.y);
        const float* bb = Bt + k8 * 320 + t4 * 80;
#pragma unroll
        for (int nt = 0; nt < 4; nt++) {
            float2 bv = *(const float2*)(bb + (nt * 8 + g) * 2);
            mma_tf32(acc[nt], a0, a1, a2, a3,
                     __float_as_uint(bv.x), __float_as_uint(bv.y));
        }
    }
}

__device__ __forceinline__ void gemmA_p2(const float* __restrict__ As,
                                         const float* __restrict__ Bt0,
                                         const float* __restrict__ Bt1,
                                         int wr, int g, int t4,
                                         float acc0[4][4], float acc1[4][4]) {
#pragma unroll
    for (int k8 = 0; k8 < 8; k8++) {
        float2 vlo = *(const float2*)(As + (wr + g) * 68 + k8 * 8 + 2 * t4);
        float2 vhi = *(const float2*)(As + (wr + g + 8) * 68 + k8 * 8 + 2 * t4);
        uint32_t a0 = __float_as_uint(vlo.x), a1 = __float_as_uint(vhi.x);
        uint32_t a2 = __float_as_uint(vlo.y), a3 = __float_as_uint(vhi.y);
        const float* bb0 = Bt0 + k8 * 320 + t4 * 80;
        const float* bb1 = Bt1 + k8 * 320 + t4 * 80;
#pragma unroll
        for (int nt = 0; nt < 4; nt++) {
            float2 bv0 = *(const float2*)(bb0 + (nt * 8 + g) * 2);
            float2 bv1 = *(const float2*)(bb1 + (nt * 8 + g) * 2);
            mma_tf32(acc0[nt], a0, a1, a2, a3,
                     __float_as_uint(bv0.x), __float_as_uint(bv0.y));
            mma_tf32(acc1[nt], a0, a1, a2, a3,
                     __float_as_uint(bv1.x), __float_as_uint(bv1.y));
        }
    }
}

__global__ __launch_bounds__(SAM_THREADS, 2) void stage_a_mma(
    const float* __restrict__ inp, const int* __restrict__ vidx, int n,
    const float* __restrict__ w1x, const float* __restrict__ b1x,
    const float* __restrict__ w2x, const float* __restrict__ b2x,
    const float* __restrict__ w1r, const float* __restrict__ b1r,
    const float* __restrict__ w2r, const float* __restrict__ b2r,
    const float* __restrict__ wax, const float* __restrict__ bax,
    const float* __restrict__ war, const float* __restrict__ bar)
{
    extern __shared__ float sm[];
    float* sW = sm;                      // 512
    float* sB = sm + 512;                // 4 x 2560 (paired layout)
    float* sA = sm + 10752;              // [128][68] paired-k (hidden, then comb)
    int*   svx = (int*)(sm + 10752 + 128 * 68);

    int t = threadIdx.x;
    int lane = t & 31, w = t >> 5;
    int g = lane >> 2, t4 = lane & 3;
    int wr = 16 * w;
    int row0 = blockIdx.x * 128;

    for (int i = t; i < 192; i += SAM_THREADS) { sW[i] = w1x[i]; sW[256 + i] = w1r[i]; }
    for (int i = t; i < 64; i += SAM_THREADS)  { sW[192 + i] = b1x[i]; sW[448 + i] = b1r[i]; }
    {
        const float* wsrc[4] = {w2x, w2r, wax, war};
#pragma unroll
        for (int a = 0; a < 4; a++) {
            float* dst = sB + a * 2560;
            const float* s = wsrc[a];
            for (int i = t; i < 2048; i += SAM_THREADS) {
                int k = i >> 5, c = i & 31;
                int off = (k >> 3) * 320 + (k & 3) * 80 + c * 2 + ((k >> 2) & 1);
                dst[off] = __uint_as_float(f2tf32(s[i]));
            }
        }
    }
    __syncthreads();

    int p = t >> 1, half = t & 1;
    int cp = min(row0 + p, n - 1);
    if (half == 0) svx[p] = vidx[cp];
    float i0 = inp[(size_t)cp * 6 + 0], i1 = inp[(size_t)cp * 6 + 1], i2 = inp[(size_t)cp * 6 + 2];
    float i3 = inp[(size_t)cp * 6 + 3], i4 = inp[(size_t)cp * 6 + 4], i5 = inp[(size_t)cp * 6 + 5];

    // layer1 xyz -> sA (paired-k positions)
    {
        const float* W = sW; const float* B = sW + 192;
        int ob = half * 32;
#pragma unroll 8
        for (int o = 0; o < 32; o++) {
            int oo = ob + o;
            float a = B[oo] + i0 * W[oo] + i1 * W[64 + oo] + i2 * W[128 + oo];
            sA[p * 68 + kperm(oo)] = tf32f(fmaxf(a, 0.f));
        }
    }
    __syncwarp();

    // GEMM fx
    float fx[4][4];
#pragma unroll
    for (int nt = 0; nt < 4; nt++)
#pragma unroll
        for (int j = 0; j < 4; j++) fx[nt][j] = 0.f;
    gemmA_p(sA, sB, wr, g, t4, fx);
    __syncwarp();

    // bias+relu fx (kept in regs); layer1 rgb -> sA (overwrite)
#pragma unroll
    for (int nt = 0; nt < 4; nt++) {
        int c = nt * 8 + 2 * t4;
        float bc0 = __ldg(b2x + c), bc1 = __ldg(b2x + c + 1);
        fx[nt][0] = fmaxf(fx[nt][0] + bc0, 0.f);
        fx[nt][1] = fmaxf(fx[nt][1] + bc1, 0.f);
        fx[nt][2] = fmaxf(fx[nt][2] + bc0, 0.f);
        fx[nt][3] = fmaxf(fx[nt][3] + bc1, 0.f);
    }
    {
        const float* W = sW + 256; const float* B = sW + 448;
        int ob = half * 32;
#pragma unroll 8
        for (int o = 0; o < 32; o++) {
            int oo = ob + o;
            float a = B[oo] + i3 * W[oo] + i4 * W[64 + oo] + i5 * W[128 + oo];
            sA[p * 68 + kperm(oo)] = tf32f(fmaxf(a, 0.f));
        }
    }
    __syncwarp();

    // GEMM fr
    float fr[4][4];
#pragma unroll
    for (int nt = 0; nt < 4; nt++)
#pragma unroll
        for (int j = 0; j < 4; j++) fr[nt][j] = 0.f;
    gemmA_p(sA, sB + 2560, wr, g, t4, fr);
    __syncwarp();

    // write comb = [fx, fr] into sA (tf32, paired-k positions)
#pragma unroll
    for (int nt = 0; nt < 4; nt++) {
        int c = nt * 8 + 2 * t4;
        float bc0 = __ldg(b2r + c), bc1 = __ldg(b2r + c + 1);
        fr[nt][0] = fmaxf(fr[nt][0] + bc0, 0.f);
        fr[nt][1] = fmaxf(fr[nt][1] + bc1, 0.f);
        fr[nt][2] = fmaxf(fr[nt][2] + bc0, 0.f);
        fr[nt][3] = fmaxf(fr[nt][3] + bc1, 0.f);
        int r = wr + g;
        int p0 = kperm(c), p1 = kperm(c + 1);
        sA[r * 68 + p0]        = tf32f(fx[nt][0]);
        sA[r * 68 + p1]        = tf32f(fx[nt][1]);
        sA[(r + 8) * 68 + p0]  = tf32f(fx[nt][2]);
        sA[(r + 8) * 68 + p1]  = tf32f(fx[nt][3]);
        sA[r * 68 + 32 + p0]       = tf32f(fr[nt][0]);
        sA[r * 68 + 32 + p1]       = tf32f(fr[nt][1]);
        sA[(r + 8) * 68 + 32 + p0] = tf32f(fr[nt][2]);
        sA[(r + 8) * 68 + 32 + p1] = tf32f(fr[nt][3]);
    }
    __syncwarp();

    // attention GEMMs (comb K=64) — fused pair, A loaded once
    float ax[4][4], ar[4][4];
#pragma unroll
    for (int nt = 0; nt < 4; nt++)
#pragma unroll
        for (int j = 0; j < 4; j++) { ax[nt][j] = 0.f; ar[nt][j] = 0.f; }
    gemmA_p2(sA, sB + 2 * 2560, sB + 3 * 2560, wr, g, t4, ax, ar);

#pragma unroll
    for (int h2 = 0; h2 < 2; h2++) {
        int r = wr + g + 8 * h2;
        int pt = row0 + r;
        if (pt < n) {
            int vr = svx[r];
            uint32_t* pfr = (uint32_t*)(g_pf2b + (size_t)pt * 128);
            float* vxr = g_vox + (size_t)vr * 128;
#pragma unroll
            for (int nt = 0; nt < 4; nt++) {
                int c = nt * 8 + 2 * t4;
                int j0 = 2 * h2, j1 = 2 * h2 + 1;
                float axa = ax[nt][j0] + __ldg(bax + c);
                float axb = ax[nt][j1] + __ldg(bax + c + 1);
                float ara = ar[nt][j0] + __ldg(bar + c);
                float arb = ar[nt][j1] + __ldg(bar + c + 1);
                float sxa = 1.f / (1.f + __expf(-axa));
                float sxb = 1.f / (1.f + __expf(-axb));
                float sra = 1.f / (1.f + __expf(-ara));
                float srb = 1.f / (1.f + __expf(-arb));
                float fxa = fx[nt][j0], fxb = fx[nt][j1];
                float fra = fr[nt][j0], frb = fr[nt][j1];
                float v1a = fxa * sxa, v1b = fxb * sxb;
                float v3a = fra * sra, v3b = frb * srb;
                int cw = c >> 1;
                pfr[cw]      = pack_bf16(fxa, fxb);
                pfr[16 + cw] = pack_bf16(v1a, v1b);
                pfr[32 + cw] = pack_bf16(fra, frb);
                pfr[48 + cw] = pack_bf16(v3a, v3b);
                amax_pos(vxr + c, fxa);        amax_pos(vxr + c + 1, fxb);
                amax_pos(vxr + 32 + c, v1a);   amax_pos(vxr + 33 + c, v1b);
                amax_pos(vxr + 64 + c, fra);   amax_pos(vxr + 65 + c, frb);
                amax_pos(vxr + 96 + c, v3a);   amax_pos(vxr + 97 + c, v3b);
            }
        }
    }
}

// ---------------------------------------------------------------------------
// Fused voxel kernel (unchanged from R14)
// ---------------------------------------------------------------------------
#define FV_A_U32  (64 * 68)
#define FV_B_U32  (2 * 5120)
#define FV_SMEM   ((FV_A_U32 + FV_B_U32 + 64) * 4)

__global__ __launch_bounds__(256, 2) void fused_vox(
    const float* __restrict__ bv1, int V)
{
    extern __shared__ uint32_t su[];
    uint32_t* sA32 = su;
    uint32_t* sB32 = su + FV_A_U32;
    uint32_t sAu = smem_u32(sA32);
    uint32_t sBu = smem_u32(sB32);
    const uint32_t bufu[2] = {sBu, sBu + 5120u * 4u};

    int t = threadIdx.x;
    int lane = t & 31, wid = t >> 5;
    int g = lane >> 2, t4 = lane & 3;
    int wm = wid & 1, wn = wid >> 1;
    int row0 = blockIdx.x * 64;

    uint32_t aA[2];
#pragma unroll
    for (int mt = 0; mt < 2; mt++)
        aA[mt] = sAu + (uint32_t)(((wm * 32 + mt * 16 + (lane & 15)) * 68 + (lane >> 4) * 4) * 4);
    uint32_t bRel1[2], bRel2[4];
    {
        int mat = lane >> 3;
        int nt_off = (mat >> 1) * 8, hf = mat & 1;
#pragma unroll
        for (int nt2 = 0; nt2 < 2; nt2++) {
            int row = wn * 32 + nt2 * 16 + nt_off + (lane & 7);
            bRel1[nt2] = (uint32_t)((row * 20 + hf * 4) * 4);
        }
#pragma unroll
        for (int nt2 = 0; nt2 < 4; nt2++) {
            int row = wn * 64 + nt2 * 16 + nt_off + (lane & 7);
            bRel2[nt2] = (uint32_t)((row * 20 + hf * 4) * 4);
        }
    }

#pragma unroll
    for (int i = 0; i < 3; i++) {
        int e = t + i * 256;
        if (e < 640) cp_async16(bufu[0] + (uint32_t)e * 16u, (const float4*)g_wv1b + e);
    }
    CP_COMMIT();

    {
        int p = t >> 2, q = t & 3;
        int cp = min(row0 + p, V - 1);
        const float4* src = (const float4*)(g_vox + (size_t)cp * 128) + q * 8;
        uint32_t* dst = sA32 + p * 68 + q * 16;
#pragma unroll
        for (int j = 0; j < 8; j++) {
            float4 v = src[j];
            dst[2 * j]     = pack_bf16(v.x, v.y);
            dst[2 * j + 1] = pack_bf16(v.z, v.w);
        }
    }

    float acc1[2][4][4];
#pragma unroll
    for (int mt = 0; mt < 2; mt++)
#pragma unroll
        for (int nt = 0; nt < 4; nt++)
#pragma unroll
            for (int j = 0; j < 4; j++) acc1[mt][nt][j] = 0.f;

    CP_WAIT0();
    __syncthreads();

#pragma unroll 1
    for (int kc = 0; kc < 4; kc++) {
        if (kc < 3) {
            const float4* ws = (const float4*)(g_wv1b + (kc + 1) * 5120);
#pragma unroll
            for (int i = 0; i < 3; i++) {
                int e = t + i * 256;
                if (e < 640) cp_async16(bufu[(kc + 1) & 1] + (uint32_t)e * 16u, ws + e);
            }
        } else {
            const float4* ws = (const float4*)g_w3top;
#pragma unroll
            for (int i = 0; i < 5; i++) {
                int e = t + i * 256;
                cp_async16(bufu[0] + (uint32_t)e * 16u, ws + e);
            }
        }
        CP_COMMIT();
        uint32_t bbase = bufu[kc & 1];
#pragma unroll
        for (int s = 0; s < 2; s++) {
            uint32_t a[2][4];
            ldsm4(a[0][0], a[0][1], a[0][2], a[0][3], aA[0] + (uint32_t)((kc * 16 + s * 8) * 4));
            ldsm4(a[1][0], a[1][1], a[1][2], a[1][3], aA[1] + (uint32_t)((kc * 16 + s * 8) * 4));
            uint32_t b[4][2];
#pragma unroll
            for (int nt2 = 0; nt2 < 2; nt2++)
                ldsm4(b[2 * nt2][0], b[2 * nt2][1], b[2 * nt2 + 1][0], b[2 * nt2 + 1][1],
                      bbase + bRel1[nt2] + (uint32_t)(s * 32));
#pragma unroll
            for (int nt = 0; nt < 4; nt++)
#pragma unroll
                for (int mt = 0; mt < 2; mt++)
                    mma_bf16(acc1[mt][nt], a[mt][0], a[mt][1], a[mt][2], a[mt][3],
                             b[nt][0], b[nt][1]);
        }
        CP_WAIT0();
        __syncthreads();
    }

#pragma unroll
    for (int mt = 0; mt < 2; mt++) {
        int r = wm * 32 + mt * 16 + g;
        int vr0 = row0 + r, vr1 = row0 + r + 8;
        uint32_t* o0 = (uint32_t*)(g_voxfb + (size_t)vr0 * 128);
        uint32_t* o1 = (uint32_t*)(g_voxfb + (size_t)vr1 * 128);
#pragma unroll
        for (int nt = 0; nt < 4; nt++) {
            int c = wn * 32 + nt * 8 + 2 * t4;
            float bc0 = __ldg(bv1 + c), bc1 = __ldg(bv1 + c + 1);
            float h0 = fmaxf(acc1[mt][nt][0] + bc0, 0.f);
            float h1 = fmaxf(acc1[mt][nt][1] + bc1, 0.f);
            float h2 = fmaxf(acc1[mt][nt][2] + bc0, 0.f);
            float h3 = fmaxf(acc1[mt][nt][3] + bc1, 0.f);
            uint32_t p01 = pack_bf16(h0, h1), p23 = pack_bf16(h2, h3);
            sA32[r * 68 + (c >> 1)]       = p01;
            sA32[(r + 8) * 68 + (c >> 1)] = p23;
            if (vr0 < V) o0[c >> 1] = p01;
            if (vr1 < V) o1[c >> 1] = p23;
        }
    }
    __syncthreads();

    float acc2[2][8][4];
#pragma unroll
    for (int mt = 0; mt < 2; mt++)
#pragma unroll
        for (int nt = 0; nt < 8; nt++)
#pragma unroll
            for (int j = 0; j < 4; j++) acc2[mt][nt][j] = 0.f;

#pragma unroll 1
    for (int kc = 0; kc < 4; kc++) {
        if (kc < 3) {
            const float4* ws = (const float4*)(g_w3top + (kc + 1) * 10240);
#pragma unroll
            for (int i = 0; i < 5; i++) {
                int e = t + i * 256;
                cp_async16(bufu[(kc + 1) & 1] + (uint32_t)e * 16u, ws + e);
            }
            CP_COMMIT();
        }
        uint32_t bbase = bufu[kc & 1];
#pragma unroll
        for (int s = 0; s < 2; s++) {
            uint32_t a[2][4];
            ldsm4(a[0][0], a[0][1], a[0][2], a[0][3], aA[0] + (uint32_t)((kc * 16 + s * 8) * 4));
            ldsm4(a[1][0], a[1][1], a[1][2], a[1][3], aA[1] + (uint32_t)((kc * 16 + s * 8) * 4));
            uint32_t b[8][2];
#pragma unroll
            for (int nt2 = 0; nt2 < 4; nt2++)
                ldsm4(b[2 * nt2][0], b[2 * nt2][1], b[2 * nt2 + 1][0], b[2 * nt2 + 1][1],
                      bbase + bRel2[nt2] + (uint32_t)(s * 32));
#pragma unroll
            for (int nt = 0; nt < 8; nt++)
#pragma unroll
                for (int mt = 0; mt < 2; mt++)
                    mma_bf16(acc2[mt][nt], a[mt][0], a[mt][1], a[mt][2], a[mt][3],
                             b[nt][0], b[nt][1]);
        }
        CP_WAIT0();
        __syncthreads();
    }

#pragma unroll
    for (int mt = 0; mt < 2; mt++) {
        int r = wm * 32 + mt * 16 + g;
        int vr0 = row0 + r, vr1 = vr0 + 8;
#pragma unroll
        for (int nt = 0; nt < 8; nt++) {
            int c = wn * 64 + nt * 8 + 2 * t4;
            if (vr0 < V)
                *(float2*)(g_voxh + (size_t)vr0 * 256 + c) =
                    make_float2(acc2[mt][nt][0], acc2[mt][nt][1]);
            if (vr1 < V)
                *(float2*)(g_voxh + (size_t)vr1 * 256 + c) =
                    make_float2(acc2[mt][nt][2], acc2[mt][nt][3]);
        }
    }
}

// ---------------------------------------------------------------------------
// Output GEMM (bf16, unchanged from R14)
// ---------------------------------------------------------------------------
template <int KC, int NT>
__global__ __launch_bounds__(256, 2) void gemm_out_bf16(
    const float* __restrict__ A, const __nv_bfloat16* __restrict__ Wimg,
    const float* __restrict__ bias, float* __restrict__ out, int M)
{
    const int K = KC * 32;
    const int AST = K / 2 + 4;
    const int NCOL = NT * 32;
    const int BCH = NCOL * 20;
    const int BCH4 = NCOL * 5;
    extern __shared__ uint32_t su[];
    uint32_t* sA32 = su;
    uint32_t* sB32 = su + 64 * AST;
    uint32_t sAu = smem_u32(sA32);
    uint32_t sBu = smem_u32(sB32);
    const uint32_t bufu[2] = {sBu, sBu + (uint32_t)BCH * 4u};

    int t = threadIdx.x;
    int lane = t & 31, wid = t >> 5;
    int g = lane >> 2, t4 = lane & 3;
    int wm = wid & 1, wn = wid >> 1;
    int row0 = blockIdx.x * 64;

    uint32_t aA[2];
#pragma unroll
    for (int mt = 0; mt < 2; mt++)
        aA[mt] = sAu + (uint32_t)(((wm * 32 + mt * 16 + (lane & 15)) * AST + (lane >> 4) * 4) * 4);
    uint32_t bBrel[NT / 2];
    {
        int mat = lane >> 3;
        int nt_off = (mat >> 1) * 8, half = mat & 1;
#pragma unroll
        for (int nt2 = 0; nt2 < NT / 2; nt2++) {
            int row = wn * (NT * 8) + nt2 * 16 + nt_off + (lane & 7);
            bBrel[nt2] = (uint32_t)((row * 20 + half * 4) * 4);
        }
    }

#pragma unroll
    for (int i = 0; i < (BCH4 + 255) / 256; i++) {
        int e = t + i * 256;
        if (e < BCH4) cp_async16(bufu[0] + (uint32_t)e * 16u, (const float4*)Wimg + e);
    }
    CP_COMMIT();

    {
        int p = t >> 2, q = t & 3;
        int cp = min(row0 + p, M - 1);
        const float4* src = (const float4*)(A + (size_t)cp * K) + q * (K / 16);
        uint32_t* dst = sA32 + p * AST + q * (K / 8);
#pragma unroll
        for (int j = 0; j < K / 16; j++) {
            float4 v = src[j];
            dst[2 * j]     = pack_bf16(v.x, v.y);
            dst[2 * j + 1] = pack_bf16(v.z, v.w);
        }
    }

    float acc[2][NT][4];
#pragma unroll
    for (int mt = 0; mt < 2; mt++)
#pragma unroll
        for (int nt = 0; nt < NT; nt++)
#pragma unroll
            for (int j = 0; j < 4; j++) acc[mt][nt][j] = 0.f;

    CP_WAIT0();
    __syncthreads();

#pragma unroll 1
    for (int kc = 0; kc < KC; kc++) {
        if (kc < KC - 1) {
            const float4* ws = (const float4*)(Wimg + (size_t)(kc + 1) * NCOL * 40);
#pragma unroll
            for (int i = 0; i < (BCH4 + 255) / 256; i++) {
                int e = t + i * 256;
                if (e < BCH4) cp_async16(bufu[(kc + 1) & 1] + (uint32_t)e * 16u, ws + e);
            }
            CP_COMMIT();
        }
        uint32_t bbase = bufu[kc & 1];
#pragma unroll
        for (int s = 0; s < 2; s++) {
            uint32_t a[2][4];
            ldsm4(a[0][0], a[0][1], a[0][2], a[0][3], aA[0] + (uint32_t)((kc * 16 + s * 8) * 4));
            ldsm4(a[1][0], a[1][1], a[1][2], a[1][3], aA[1] + (uint32_t)((kc * 16 + s * 8) * 4));
            uint32_t b[NT][2];
#pragma unroll
            for (int nt2 = 0; nt2 < NT / 2; nt2++)
                ldsm4(b[2 * nt2][0], b[2 * nt2][1], b[2 * nt2 + 1][0], b[2 * nt2 + 1][1],
                      bbase + bBrel[nt2] + (uint32_t)(s * 32));
#pragma unroll
            for (int nt = 0; nt < NT; nt++)
#pragma unroll
                for (int mt = 0; mt < 2; mt++)
                    mma_bf16(acc[mt][nt], a[mt][0], a[mt][1], a[mt][2], a[mt][3],
                             b[nt][0], b[nt][1]);
        }
        CP_WAIT0();
        __syncthreads();
    }

#pragma unroll
    for (int mt = 0; mt < 2; mt++) {
        int lr = wm * 32 + mt * 16 + g;
        int r0 = row0 + lr, r1 = r0 + 8;
#pragma unroll
        for (int nt = 0; nt < NT; nt++) {
            int c = wn * (NT * 8) + nt * 8 + 2 * t4;
            float bc0 = __ldg(bias + c), bc1 = __ldg(bias + c + 1);
            if (r0 < M)
                *(float2*)(out + (size_t)r0 * NCOL + c) =
                    make_float2(fmaxf(acc[mt][nt][0] + bc0, 0.f), fmaxf(acc[mt][nt][1] + bc1, 0.f));
            if (r1 < M)
                *(float2*)(out + (size_t)r1 * NCOL + c) =
                    make_float2(fmaxf(acc[mt][nt][2] + bc0, 0.f), fmaxf(acc[mt][nt][3] + bc1, 0.f));
        }
    }
}

// ---------------------------------------------------------------------------
// Stage C v6 (unchanged from R14)
// ---------------------------------------------------------------------------
#define SC4_A_U32   (64 * 132)
#define SC4_B_U32   (2 * 5120)
#define SC4_SMEM    ((SC4_A_U32 + SC4_B_U32 + 64) * 4)

__device__ __forceinline__ void ldBb_async(const __nv_bfloat16* __restrict__ ws,
                                           uint32_t dstu, int t) {
#pragma unroll
    for (int i = 0; i < 5; i++) {
        int e = t + i * 256;
        cp_async16(dstu + (uint32_t)e * 16u, (const float4*)ws + e);
    }
}

__global__ __launch_bounds__(256, 2) void stage_c_bf16(
    const int* __restrict__ vidx, int n,
    const float* __restrict__ b3, const float* __restrict__ b4)
{
    extern __shared__ uint32_t su[];
    uint32_t* sA32 = su;
    uint32_t* sB32 = su + SC4_A_U32;
    int* svx = (int*)(su + SC4_A_U32 + SC4_B_U32);
    uint32_t sAu = smem_u32(sA32);
    uint32_t sBu = smem_u32(sB32);
    const uint32_t bufu[2] = {sBu, sBu + 5120u * 4u};

    int t = threadIdx.x;
    int lane = t & 31, wid = t >> 5;
    int g = lane >> 2, t4 = lane & 3;
    int wm = wid & 1, wn = wid >> 1;
    int row0 = blockIdx.x * 64;

    uint32_t aA[2];
#pragma unroll
    for (int mt = 0; mt < 2; mt++)
        aA[mt] = sAu + (uint32_t)(((wm * 32 + mt * 16 + (lane & 15)) * 132 + (lane >> 4) * 4) * 4);
    uint32_t bBrel[4];
    {
        int mat = lane >> 3;
        int nt_off = (mat >> 1) * 8, half = mat & 1;
#pragma unroll
        for (int nt2 = 0; nt2 < 4; nt2++) {
            int row = wn * 64 + nt2 * 16 + nt_off + (lane & 7);
            bBrel[nt2] = (uint32_t)((row * 20 + half * 4) * 4);
        }
    }

    ldBb_async(g_w3bot, bufu[0], t);
    CP_COMMIT();

    {
        int p = t >> 2, q = t & 3;
        int pt = row0 + p;
        int cp = min(pt, n - 1);
        if (q == 0) svx[p] = vidx[cp];
        const uint4* src = (const uint4*)(g_pf2b + (size_t)cp * 128) + q * 4;
        uint4* dst = (uint4*)(sA32 + p * 132) + q * 4;
#pragma unroll
        for (int j = 0; j < 4; j++) dst[j] = src[j];
    }

    float acc[2][8][4];
#pragma unroll
    for (int mt = 0; mt < 2; mt++)
#pragma unroll
        for (int nt = 0; nt < 8; nt++)
#pragma unroll
            for (int j = 0; j < 4; j++) acc[mt][nt][j] = 0.f;

    CP_WAIT0();
    __syncthreads();

#pragma unroll 1
    for (int kc = 0; kc < 4; kc++) {
        if (kc < 3) {
            ldBb_async(g_w3bot + (kc + 1) * 10240, bufu[(kc + 1) & 1], t);
        } else {
            ldBb_async(g_w4b, bufu[0], t);
        }
        CP_COMMIT();
        uint32_t bbase = bufu[kc & 1];
#pragma unroll
        for (int s = 0; s < 2; s++) {
            uint32_t a[2][4];
            ldsm4(a[0][0], a[0][1], a[0][2], a[0][3], aA[0] + (uint32_t)((kc * 16 + s * 8) * 4));
            ldsm4(a[1][0], a[1][1], a[1][2], a[1][3], aA[1] + (uint32_t)((kc * 16 + s * 8) * 4));
            uint32_t b[8][2];
#pragma unroll
            for (int nt2 = 0; nt2 < 4; nt2++)
                ldsm4(b[2 * nt2][0], b[2 * nt2][1], b[2 * nt2 + 1][0], b[2 * nt2 + 1][1],
                      bbase + bBrel[nt2] + (uint32_t)(s * 32));
#pragma unroll
            for (int nt = 0; nt < 8; nt++)
#pragma unroll
                for (int mt = 0; mt < 2; mt++)
                    mma_bf16(acc[mt][nt], a[mt][0], a[mt][1], a[mt][2], a[mt][3],
                             b[nt][0], b[nt][1]);
        }
        CP_WAIT0();
        __syncthreads();
    }

#pragma unroll
    for (int mt = 0; mt < 2; mt++) {
        int r = wm * 32 + mt * 16 + g;
        const float* vh0 = g_voxh + (size_t)svx[r] * 256;
        const float* vh1 = g_voxh + (size_t)svx[r + 8] * 256;
#pragma unroll
        for (int nt = 0; nt < 8; nt++) {
            int c = wn * 64 + nt * 8 + 2 * t4;
            float bc0 = __ldg(b3 + c), bc1 = __ldg(b3 + c + 1);
            float2 h0v = *(const float2*)(vh0 + c);
            float2 h1v = *(const float2*)(vh1 + c);
            float h0 = fmaxf(acc[mt][nt][0] + h0v.x + bc0, 0.f);
            float h1 = fmaxf(acc[mt][nt][1] + h0v.y + bc1, 0.f);
            float h2 = fmaxf(acc[mt][nt][2] + h1v.x + bc0, 0.f);
            float h3 = fmaxf(acc[mt][nt][3] + h1v.y + bc1, 0.f);
            sA32[r * 132 + (c >> 1)]       = pack_bf16(h0, h1);
            sA32[(r + 8) * 132 + (c >> 1)] = pack_bf16(h2, h3);
            acc[mt][nt][0] = 0.f; acc[mt][nt][1] = 0.f;
            acc[mt][nt][2] = 0.f; acc[mt][nt][3] = 0.f;
        }
    }
    __syncthreads();

#pragma unroll 1
    for (int kc = 0; kc < 8; kc++) {
        if (kc < 7) {
            ldBb_async(g_w4b + (kc + 1) * 10240, bufu[(kc + 1) & 1], t);
            CP_COMMIT();
        }
        uint32_t bbase = bufu[kc & 1];
#pragma unroll
        for (int s = 0; s < 2; s++) {
            uint32_t a[2][4];
            ldsm4(a[0][0], a[0][1], a[0][2], a[0][3], aA[0] + (uint32_t)((kc * 16 + s * 8) * 4));
            ldsm4(a[1][0], a[1][1], a[1][2], a[1][3], aA[1] + (uint32_t)((kc * 16 + s * 8) * 4));
            uint32_t b[8][2];
#pragma unroll
            for (int nt2 = 0; nt2 < 4; nt2++)
                ldsm4(b[2 * nt2][0], b[2 * nt2][1], b[2 * nt2 + 1][0], b[2 * nt2 + 1][1],
                      bbase + bBrel[nt2] + (uint32_t)(s * 32));
#pragma unroll
            for (int nt = 0; nt < 8; nt++)
#pragma unroll
                for (int mt = 0; mt < 2; mt++)
                    mma_bf16(acc[mt][nt], a[mt][0], a[mt][1], a[mt][2], a[mt][3],
                             b[nt][0], b[nt][1]);
        }
        CP_WAIT0();
        __syncthreads();
    }

#pragma unroll
    for (int mt = 0; mt < 2; mt++) {
        int lr = wm * 32 + mt * 16 + g;
        int pt0 = row0 + lr, pt1 = pt0 + 8;
        int vr0 = svx[lr], vr1 = svx[lr + 8];
        bool ok0 = pt0 < n, ok1 = pt1 < n;
        float* d0 = g_vox2 + (size_t)vr0 * 256;
        float* d1 = g_vox2 + (size_t)vr1 * 256;
#pragma unroll
        for (int nt = 0; nt < 8; nt++) {
            int c = wn * 64 + nt * 8 + 2 * t4;
            float bc0 = __ldg(b4 + c), bc1 = __ldg(b4 + c + 1);
            if (ok0) {
                amax_pos(d0 + c,     acc[mt][nt][0] + bc0);
                amax_pos(d0 + c + 1, acc[mt][nt][1] + bc1);
            }
            if (ok1) {
                amax_pos(d1 + c,     acc[mt][nt][2] + bc0);
                amax_pos(d1 + c + 1, acc[mt][nt][3] + bc1);
            }
        }
    }
}

// ---------------------------------------------------------------------------
extern "C" void kernel_launch(void* const* d_in, const int* in_sizes, int n_in,
                              void* d_out, int out_size)
{
    const float* inp  = (const float*)d_in[0];
    const int*   vidx = (const int*)d_in[1];
    int base = (n_in >= 23) ? 3 : 2;
    const float* w1x = (const float*)d_in[base + 0];
    const float* b1x = (const float*)d_in[base + 1];
    const float* w2x = (const float*)d_in[base + 2];
    const float* b2x = (const float*)d_in[base + 3];
    const float* w1r = (const float*)d_in[base + 4];
    const float* b1r = (const float*)d_in[base + 5];
    const float* w2r = (const float*)d_in[base + 6];
    const float* b2r = (const float*)d_in[base + 7];
    const float* wax = (const float*)d_in[base + 8];
    const float* bax = (const float*)d_in[base + 9];
    const float* war = (const float*)d_in[base + 10];
    const float* bar = (const float*)d_in[base + 11];
    const float* wv1 = (const float*)d_in[base + 12];
    const float* bv1 = (const float*)d_in[base + 13];
    const float* w3  = (const float*)d_in[base + 14];
    const float* b3  = (const float*)d_in[base + 15];
    const float* w4  = (const float*)d_in[base + 16];
    const float* b4  = (const float*)d_in[base + 17];
    const float* wv2 = (const float*)d_in[base + 18];
    const float* bv2 = (const float*)d_in[base + 19];

    int n = in_sizes[0] / 6;
    int V = out_size / 256;

    const int GO_SMEM = (64 * 132 + 2 * 5120 + 64) * 4;

    auto kOut = gemm_out_bf16<8, 8>;

    cudaFuncSetAttribute(stage_a_mma, cudaFuncAttributeMaxDynamicSharedMemorySize, SAM_SMEM);
    cudaFuncSetAttribute(stage_c_bf16, cudaFuncAttributeMaxDynamicSharedMemorySize, SC4_SMEM);
    cudaFuncSetAttribute(fused_vox, cudaFuncAttributeMaxDynamicSharedMemorySize, FV_SMEM);
    cudaFuncSetAttribute(kOut, cudaFuncAttributeMaxDynamicSharedMemorySize, GO_SMEM);

    float *p_vox2;
    __nv_bfloat16 *p_wvb;
    cudaGetSymbolAddress((void**)&p_vox2, g_vox2);
    cudaGetSymbolAddress((void**)&p_wvb, g_wvb);

    int zb = (V * 256 + 255) / 256;
    zero_k<<<zb, 256>>>(V * 128, V * 256);
    prep_all<<<1040, 256>>>(w3, w4, wv2, wv1);

    stage_a_mma<<<(n + 127) / 128, SAM_THREADS, SAM_SMEM>>>(
        inp, vidx, n, w1x, b1x, w2x, b2x, w1r, b1r, w2r, b2r, wax, bax, war, bar);

    fused_vox<<<(V + 63) / 64, 256, FV_SMEM>>>(bv1, V);

    stage_c_bf16<<<(n + 63) / 64, 256, SC4_SMEM>>>(vidx, n, b3, b4);

    kOut<<<(V + 63) / 64, 256, GO_SMEM>>>(p_vox2, p_wvb, bv2, (float*)d_out, V);
}

// round 16
// speedup vs baseline: 1.0745x; 1.0745x over previous
#include <cuda_runtime.h>
#include <cuda_bf16.h>
#include <cstdint>
#include <math.h>

#define MAXN 500000
#define MAXV 50000

// ---- scratch (static __device__ arrays; allocation-free) ----
__device__ __align__(128) __nv_bfloat16 g_pf2b[(size_t)MAXN * 128];   // pf2 bf16
__device__ __align__(128) float g_vox[(size_t)MAXV * 128];
__device__ __align__(128) __nv_bfloat16 g_voxfb[(size_t)MAXV * 128];  // voxf bf16
__device__ __align__(128) float g_voxh[(size_t)MAXV * 256];           // voxf @ w3_top
__device__ __align__(128) float g_vox2[(size_t)MAXV * 256];
__device__ __align__(128) __nv_bfloat16 g_w3top[40960];  // w3 rows 0..127  [4][256][40]
__device__ __align__(128) __nv_bfloat16 g_w3bot[40960];  // w3 rows 128..255
__device__ __align__(128) __nv_bfloat16 g_w4b[81920];    // w4 [8][256][40]
__device__ __align__(128) __nv_bfloat16 g_wvb[81920];    // wv2
__device__ __align__(128) __nv_bfloat16 g_wv1b[20480];   // wv1 [4][128][40]

__device__ __forceinline__ void amax_pos(float* addr, float v) {
    if (v > 0.f) atomicMax((int*)addr, __float_as_int(v));
}

__device__ __forceinline__ uint32_t f2tf32(float f) {
    uint32_t r;
    asm("cvt.rna.tf32.f32 %0, %1;" : "=r"(r) : "f"(f));
    return r;
}
__device__ __forceinline__ float tf32f(float f) { return __uint_as_float(f2tf32(f)); }

__device__ __forceinline__ uint32_t pack_bf16(float a, float b) {
    __nv_bfloat162 h = __floats2bfloat162_rn(a, b);
    uint32_t r;
    memcpy(&r, &h, 4);
    return r;
}

__device__ __forceinline__ uint32_t smem_u32(const void* p) {
    return (uint32_t)__cvta_generic_to_shared(p);
}
__device__ __forceinline__ void cp_async16(uint32_t dst, const void* src) {
    asm volatile("cp.async.cg.shared.global [%0], [%1], 16;" :: "r"(dst), "l"(src));
}
#define CP_COMMIT() asm volatile("cp.async.commit_group;" ::: "memory")
#define CP_WAIT0()  asm volatile("cp.async.wait_group 0;" ::: "memory")

__device__ __forceinline__ void ldsm4(uint32_t& r0, uint32_t& r1, uint32_t& r2,
                                      uint32_t& r3, uint32_t addr) {
    asm volatile("ldmatrix.sync.aligned.m8n8.x4.shared.b16 {%0,%1,%2,%3}, [%4];"
                 : "=r"(r0), "=r"(r1), "=r"(r2), "=r"(r3) : "r"(addr));
}

__device__ __forceinline__ void mma_bf16(float acc[4], uint32_t a0, uint32_t a1,
                                         uint32_t a2, uint32_t a3, uint32_t b0, uint32_t b1) {
    asm volatile(
        "mma.sync.aligned.m16n8k16.row.col.f32.bf16.bf16.f32 "
        "{%0,%1,%2,%3},{%4,%5,%6,%7},{%8,%9},{%0,%1,%2,%3};"
        : "+f"(acc[0]), "+f"(acc[1]), "+f"(acc[2]), "+f"(acc[3])
        : "r"(a0), "r"(a1), "r"(a2), "r"(a3), "r"(b0), "r"(b1));
}

__device__ __forceinline__ void mma_tf32(float acc[4], uint32_t a0, uint32_t a1,
                                         uint32_t a2, uint32_t a3, uint32_t b0, uint32_t b1) {
    asm volatile(
        "mma.sync.aligned.m16n8k8.row.col.f32.tf32.tf32.f32 "
        "{%0,%1,%2,%3},{%4,%5,%6,%7},{%8,%9},{%0,%1,%2,%3};"
        : "+f"(acc[0]), "+f"(acc[1]), "+f"(acc[2]), "+f"(acc[3])
        : "r"(a0), "r"(a1), "r"(a2), "r"(a3), "r"(b0), "r"(b1));
}

// ---------------------------------------------------------------------------
// init_all: zero segment-max accumulators AND build blocked bf16 weight
// images in ONE launch (grid-stride both ranges).
// ---------------------------------------------------------------------------
__device__ __forceinline__ void blk_one(const float* __restrict__ w,
                                        __nv_bfloat16* __restrict__ d, int j, int NCOL) {
    int per = NCOL * 40;
    int kc = j / per, rem = j % per, nn = rem / 40, kl = rem % 40;
    float v = (kl < 32) ? w[(size_t)(kc * 32 + kl) * NCOL + nn] : 0.f;
    d[j] = __float2bfloat16(v);
}

__global__ void init_all(const float* __restrict__ w3, const float* __restrict__ w4,
                         const float* __restrict__ wv2, const float* __restrict__ wv1,
                         int na, int nb) {
    int i = blockIdx.x * blockDim.x + threadIdx.x;
    int stride = gridDim.x * blockDim.x;
    for (int j = i; j < nb; j += stride) {
        if (j < na) g_vox[j] = 0.f;
        g_vox2[j] = 0.f;
    }
    for (int j = i; j < 266240; j += stride) {
        if (j < 40960) blk_one(w3, g_w3top, j, 256);
        else if (j < 81920) blk_one(w3 + 128 * 256, g_w3bot, j - 40960, 256);
        else if (j < 163840) blk_one(w4, g_w4b, j - 81920, 256);
        else if (j < 245760) blk_one(wv2, g_wvb, j - 163840, 256);
        else blk_one(wv1, g_wv1b, j - 245760, 128);
    }
}

// ---------------------------------------------------------------------------
// warp micro-GEMM helper: [16x64]@[64x32] tf32, A stride 68, B stride 40
// ---------------------------------------------------------------------------
__device__ __forceinline__ void gemm64x32(const float* __restrict__ As,
                                          const float* __restrict__ Bt,
                                          int wr, int g, int t4, float acc[4][4]) {
#pragma unroll
    for (int k8 = 0; k8 < 8; k8++) {
        const float* ap = As + (wr + g) * 68 + k8 * 8 + t4;
        uint32_t a0 = __float_as_uint(ap[0]);
        uint32_t a1 = __float_as_uint(ap[8 * 68]);
        uint32_t a2 = __float_as_uint(ap[4]);
        uint32_t a3 = __float_as_uint(ap[8 * 68 + 4]);
#pragma unroll
        for (int nt = 0; nt < 4; nt++) {
            const float* bp = Bt + (k8 * 8 + t4) * 40 + nt * 8 + g;
            uint32_t b0 = __float_as_uint(bp[0]);
            uint32_t b1 = __float_as_uint(bp[4 * 40]);
            mma_tf32(acc[nt], a0, a1, a2, a3, b0, b1);
        }
    }
}

// ---------------------------------------------------------------------------
// Stage A via mma.sync tf32 (R14 known-good: sC removed, 2 CTA/SM)
// ---------------------------------------------------------------------------
#define SAM_THREADS 256
#define SAM_SMEM ((512 + 10240 + 128 * 68 + 128) * 4)

__global__ __launch_bounds__(SAM_THREADS, 2) void stage_a_mma(
    const float* __restrict__ inp, const int* __restrict__ vidx, int n,
    const float* __restrict__ w1x, const float* __restrict__ b1x,
    const float* __restrict__ w2x, const float* __restrict__ b2x,
    const float* __restrict__ w1r, const float* __restrict__ b1r,
    const float* __restrict__ w2r, const float* __restrict__ b2r,
    const float* __restrict__ wax, const float* __restrict__ bax,
    const float* __restrict__ war, const float* __restrict__ bar)
{
    extern __shared__ float sm[];
    float* sW = sm;                      // 512
    float* sB = sm + 512;                // 4 x 2560
    float* sA = sm + 10752;              // [128][68]  (hidden, then comb)
    int*   svx = (int*)(sm + 10752 + 128 * 68);

    int t = threadIdx.x;
    int lane = t & 31, w = t >> 5;
    int g = lane >> 2, t4 = lane & 3;
    int wr = 16 * w;
    int row0 = blockIdx.x * 128;

    for (int i = t; i < 192; i += SAM_THREADS) { sW[i] = w1x[i]; sW[256 + i] = w1r[i]; }
    for (int i = t; i < 64; i += SAM_THREADS)  { sW[192 + i] = b1x[i]; sW[448 + i] = b1r[i]; }
    {
        const float* wsrc[4] = {w2x, w2r, wax, war};
#pragma unroll
        for (int a = 0; a < 4; a++) {
            float* dst = sB + a * 2560;
            const float* s = wsrc[a];
            for (int i = t; i < 2048; i += SAM_THREADS) {
                int k = i >> 5, c = i & 31;
                dst[k * 40 + c] = __uint_as_float(f2tf32(s[i]));
            }
        }
    }
    __syncthreads();

    int p = t >> 1, half = t & 1;
    int cp = min(row0 + p, n - 1);
    if (half == 0) svx[p] = vidx[cp];
    float i0 = inp[(size_t)cp * 6 + 0], i1 = inp[(size_t)cp * 6 + 1], i2 = inp[(size_t)cp * 6 + 2];
    float i3 = inp[(size_t)cp * 6 + 3], i4 = inp[(size_t)cp * 6 + 4], i5 = inp[(size_t)cp * 6 + 5];

    // layer1 xyz -> sA
    {
        const float* W = sW; const float* B = sW + 192;
        int ob = half * 32;
#pragma unroll 8
        for (int o = 0; o < 32; o++) {
            int oo = ob + o;
            float a = B[oo] + i0 * W[oo] + i1 * W[64 + oo] + i2 * W[128 + oo];
            sA[p * 68 + oo] = tf32f(fmaxf(a, 0.f));
        }
    }
    __syncwarp();

    // GEMM fx
    float fx[4][4];
#pragma unroll
    for (int nt = 0; nt < 4; nt++)
#pragma unroll
        for (int j = 0; j < 4; j++) fx[nt][j] = 0.f;
    gemm64x32(sA, sB, wr, g, t4, fx);
    __syncwarp();

    // bias+relu fx (kept in regs); layer1 rgb -> sA (overwrite)
#pragma unroll
    for (int nt = 0; nt < 4; nt++) {
        int c = nt * 8 + 2 * t4;
        float bc0 = __ldg(b2x + c), bc1 = __ldg(b2x + c + 1);
        fx[nt][0] = fmaxf(fx[nt][0] + bc0, 0.f);
        fx[nt][1] = fmaxf(fx[nt][1] + bc1, 0.f);
        fx[nt][2] = fmaxf(fx[nt][2] + bc0, 0.f);
        fx[nt][3] = fmaxf(fx[nt][3] + bc1, 0.f);
    }
    {
        const float* W = sW + 256; const float* B = sW + 448;
        int ob = half * 32;
#pragma unroll 8
        for (int o = 0; o < 32; o++) {
            int oo = ob + o;
            float a = B[oo] + i3 * W[oo] + i4 * W[64 + oo] + i5 * W[128 + oo];
            sA[p * 68 + oo] = tf32f(fmaxf(a, 0.f));
        }
    }
    __syncwarp();

    // GEMM fr
    float fr[4][4];
#pragma unroll
    for (int nt = 0; nt < 4; nt++)
#pragma unroll
        for (int j = 0; j < 4; j++) fr[nt][j] = 0.f;
    gemm64x32(sA, sB + 2560, wr, g, t4, fr);
    __syncwarp();

    // write comb = [fx, fr] into sA (tf32), overwriting the dead hidden tile
#pragma unroll
    for (int nt = 0; nt < 4; nt++) {
        int c = nt * 8 + 2 * t4;
        float bc0 = __ldg(b2r + c), bc1 = __ldg(b2r + c + 1);
        fr[nt][0] = fmaxf(fr[nt][0] + bc0, 0.f);
        fr[nt][1] = fmaxf(fr[nt][1] + bc1, 0.f);
        fr[nt][2] = fmaxf(fr[nt][2] + bc0, 0.f);
        fr[nt][3] = fmaxf(fr[nt][3] + bc1, 0.f);
        int r = wr + g;
        *(float2*)(sA + r * 68 + c) = make_float2(tf32f(fx[nt][0]), tf32f(fx[nt][1]));
        *(float2*)(sA + (r + 8) * 68 + c) = make_float2(tf32f(fx[nt][2]), tf32f(fx[nt][3]));
        *(float2*)(sA + r * 68 + 32 + c) = make_float2(tf32f(fr[nt][0]), tf32f(fr[nt][1]));
        *(float2*)(sA + (r + 8) * 68 + 32 + c) = make_float2(tf32f(fr[nt][2]), tf32f(fr[nt][3]));
    }
    __syncwarp();

    // attention GEMMs (comb K=64)
    float ax[4][4], ar[4][4];
#pragma unroll
    for (int nt = 0; nt < 4; nt++)
#pragma unroll
        for (int j = 0; j < 4; j++) { ax[nt][j] = 0.f; ar[nt][j] = 0.f; }
    gemm64x32(sA, sB + 2 * 2560, wr, g, t4, ax);
    gemm64x32(sA, sB + 3 * 2560, wr, g, t4, ar);

#pragma unroll
    for (int h2 = 0; h2 < 2; h2++) {
        int r = wr + g + 8 * h2;
        int pt = row0 + r;
        if (pt < n) {
            int vr = svx[r];
            uint32_t* pfr = (uint32_t*)(g_pf2b + (size_t)pt * 128);
            float* vxr = g_vox + (size_t)vr * 128;
#pragma unroll
            for (int nt = 0; nt < 4; nt++) {
                int c = nt * 8 + 2 * t4;
                int j0 = 2 * h2, j1 = 2 * h2 + 1;
                float axa = ax[nt][j0] + __ldg(bax + c);
                float axb = ax[nt][j1] + __ldg(bax + c + 1);
                float ara = ar[nt][j0] + __ldg(bar + c);
                float arb = ar[nt][j1] + __ldg(bar + c + 1);
                float sxa = 1.f / (1.f + __expf(-axa));
                float sxb = 1.f / (1.f + __expf(-axb));
                float sra = 1.f / (1.f + __expf(-ara));
                float srb = 1.f / (1.f + __expf(-arb));
                float fxa = fx[nt][j0], fxb = fx[nt][j1];
                float fra = fr[nt][j0], frb = fr[nt][j1];
                float v1a = fxa * sxa, v1b = fxb * sxb;
                float v3a = fra * sra, v3b = frb * srb;
                int cw = c >> 1;
                pfr[cw]      = pack_bf16(fxa, fxb);
                pfr[16 + cw] = pack_bf16(v1a, v1b);
                pfr[32 + cw] = pack_bf16(fra, frb);
                pfr[48 + cw] = pack_bf16(v3a, v3b);
                amax_pos(vxr + c, fxa);        amax_pos(vxr + c + 1, fxb);
                amax_pos(vxr + 32 + c, v1a);   amax_pos(vxr + 33 + c, v1b);
                amax_pos(vxr + 64 + c, fra);   amax_pos(vxr + 65 + c, frb);
                amax_pos(vxr + 96 + c, v3a);   amax_pos(vxr + 97 + c, v3b);
            }
        }
    }
}

// ---------------------------------------------------------------------------
// Fused voxel kernel (unchanged from R14)
// ---------------------------------------------------------------------------
#define FV_A_U32  (64 * 68)
#define FV_B_U32  (2 * 5120)
#define FV_SMEM   ((FV_A_U32 + FV_B_U32 + 64) * 4)

__global__ __launch_bounds__(256, 2) void fused_vox(
    const float* __restrict__ bv1, int V)
{
    extern __shared__ uint32_t su[];
    uint32_t* sA32 = su;
    uint32_t* sB32 = su + FV_A_U32;
    uint32_t sAu = smem_u32(sA32);
    uint32_t sBu = smem_u32(sB32);
    const uint32_t bufu[2] = {sBu, sBu + 5120u * 4u};

    int t = threadIdx.x;
    int lane = t & 31, wid = t >> 5;
    int g = lane >> 2, t4 = lane & 3;
    int wm = wid & 1, wn = wid >> 1;
    int row0 = blockIdx.x * 64;

    uint32_t aA[2];
#pragma unroll
    for (int mt = 0; mt < 2; mt++)
        aA[mt] = sAu + (uint32_t)(((wm * 32 + mt * 16 + (lane & 15)) * 68 + (lane >> 4) * 4) * 4);
    uint32_t bRel1[2], bRel2[4];
    {
        int mat = lane >> 3;
        int nt_off = (mat >> 1) * 8, hf = mat & 1;
#pragma unroll
        for (int nt2 = 0; nt2 < 2; nt2++) {
            int row = wn * 32 + nt2 * 16 + nt_off + (lane & 7);
            bRel1[nt2] = (uint32_t)((row * 20 + hf * 4) * 4);
        }
#pragma unroll
        for (int nt2 = 0; nt2 < 4; nt2++) {
            int row = wn * 64 + nt2 * 16 + nt_off + (lane & 7);
            bRel2[nt2] = (uint32_t)((row * 20 + hf * 4) * 4);
        }
    }

#pragma unroll
    for (int i = 0; i < 3; i++) {
        int e = t + i * 256;
        if (e < 640) cp_async16(bufu[0] + (uint32_t)e * 16u, (const float4*)g_wv1b + e);
    }
    CP_COMMIT();

    {
        int p = t >> 2, q = t & 3;
        int cp = min(row0 + p, V - 1);
        const float4* src = (const float4*)(g_vox + (size_t)cp * 128) + q * 8;
        uint32_t* dst = sA32 + p * 68 + q * 16;
#pragma unroll
        for (int j = 0; j < 8; j++) {
            float4 v = src[j];
            dst[2 * j]     = pack_bf16(v.x, v.y);
            dst[2 * j + 1] = pack_bf16(v.z, v.w);
        }
    }

    float acc1[2][4][4];
#pragma unroll
    for (int mt = 0; mt < 2; mt++)
#pragma unroll
        for (int nt = 0; nt < 4; nt++)
#pragma unroll
            for (int j = 0; j < 4; j++) acc1[mt][nt][j] = 0.f;

    CP_WAIT0();
    __syncthreads();

#pragma unroll 1
    for (int kc = 0; kc < 4; kc++) {
        if (kc < 3) {
            const float4* ws = (const float4*)(g_wv1b + (kc + 1) * 5120);
#pragma unroll
            for (int i = 0; i < 3; i++) {
                int e = t + i * 256;
                if (e < 640) cp_async16(bufu[(kc + 1) & 1] + (uint32_t)e * 16u, ws + e);
            }
        } else {
            const float4* ws = (const float4*)g_w3top;
#pragma unroll
            for (int i = 0; i < 5; i++) {
                int e = t + i * 256;
                cp_async16(bufu[0] + (uint32_t)e * 16u, ws + e);
            }
        }
        CP_COMMIT();
        uint32_t bbase = bufu[kc & 1];
#pragma unroll
        for (int s = 0; s < 2; s++) {
            uint32_t a[2][4];
            ldsm4(a[0][0], a[0][1], a[0][2], a[0][3], aA[0] + (uint32_t)((kc * 16 + s * 8) * 4));
            ldsm4(a[1][0], a[1][1], a[1][2], a[1][3], aA[1] + (uint32_t)((kc * 16 + s * 8) * 4));
            uint32_t b[4][2];
#pragma unroll
            for (int nt2 = 0; nt2 < 2; nt2++)
                ldsm4(b[2 * nt2][0], b[2 * nt2][1], b[2 * nt2 + 1][0], b[2 * nt2 + 1][1],
                      bbase + bRel1[nt2] + (uint32_t)(s * 32));
#pragma unroll
            for (int nt = 0; nt < 4; nt++)
#pragma unroll
                for (int mt = 0; mt < 2; mt++)
                    mma_bf16(acc1[mt][nt], a[mt][0], a[mt][1], a[mt][2], a[mt][3],
                             b[nt][0], b[nt][1]);
        }
        CP_WAIT0();
        __syncthreads();
    }

#pragma unroll
    for (int mt = 0; mt < 2; mt++) {
        int r = wm * 32 + mt * 16 + g;
        int vr0 = row0 + r, vr1 = row0 + r + 8;
        uint32_t* o0 = (uint32_t*)(g_voxfb + (size_t)vr0 * 128);
        uint32_t* o1 = (uint32_t*)(g_voxfb + (size_t)vr1 * 128);
#pragma unroll
        for (int nt = 0; nt < 4; nt++) {
            int c = wn * 32 + nt * 8 + 2 * t4;
            float bc0 = __ldg(bv1 + c), bc1 = __ldg(bv1 + c + 1);
            float h0 = fmaxf(acc1[mt][nt][0] + bc0, 0.f);
            float h1 = fmaxf(acc1[mt][nt][1] + bc1, 0.f);
            float h2 = fmaxf(acc1[mt][nt][2] + bc0, 0.f);
            float h3 = fmaxf(acc1[mt][nt][3] + bc1, 0.f);
            uint32_t p01 = pack_bf16(h0, h1), p23 = pack_bf16(h2, h3);
            sA32[r * 68 + (c >> 1)]       = p01;
            sA32[(r + 8) * 68 + (c >> 1)] = p23;
            if (vr0 < V) o0[c >> 1] = p01;
            if (vr1 < V) o1[c >> 1] = p23;
        }
    }
    __syncthreads();

    float acc2[2][8][4];
#pragma unroll
    for (int mt = 0; mt < 2; mt++)
#pragma unroll
        for (int nt = 0; nt < 8; nt++)
#pragma unroll
            for (int j = 0; j < 4; j++) acc2[mt][nt][j] = 0.f;

#pragma unroll 1
    for (int kc = 0; kc < 4; kc++) {
        if (kc < 3) {
            const float4* ws = (const float4*)(g_w3top + (kc + 1) * 10240);
#pragma unroll
            for (int i = 0; i < 5; i++) {
                int e = t + i * 256;
                cp_async16(bufu[(kc + 1) & 1] + (uint32_t)e * 16u, ws + e);
            }
            CP_COMMIT();
        }
        uint32_t bbase = bufu[kc & 1];
#pragma unroll
        for (int s = 0; s < 2; s++) {
            uint32_t a[2][4];
            ldsm4(a[0][0], a[0][1], a[0][2], a[0][3], aA[0] + (uint32_t)((kc * 16 + s * 8) * 4));
            ldsm4(a[1][0], a[1][1], a[1][2], a[1][3], aA[1] + (uint32_t)((kc * 16 + s * 8) * 4));
            uint32_t b[8][2];
#pragma unroll
            for (int nt2 = 0; nt2 < 4; nt2++)
                ldsm4(b[2 * nt2][0], b[2 * nt2][1], b[2 * nt2 + 1][0], b[2 * nt2 + 1][1],
                      bbase + bRel2[nt2] + (uint32_t)(s * 32));
#pragma unroll
            for (int nt = 0; nt < 8; nt++)
#pragma unroll
                for (int mt = 0; mt < 2; mt++)
                    mma_bf16(acc2[mt][nt], a[mt][0], a[mt][1], a[mt][2], a[mt][3],
                             b[nt][0], b[nt][1]);
        }
        if (kc < 3) {
            CP_WAIT0();
            __syncthreads();
        }
    }

#pragma unroll
    for (int mt = 0; mt < 2; mt++) {
        int r = wm * 32 + mt * 16 + g;
        int vr0 = row0 + r, vr1 = vr0 + 8;
#pragma unroll
        for (int nt = 0; nt < 8; nt++) {
            int c = wn * 64 + nt * 8 + 2 * t4;
            if (vr0 < V)
                *(float2*)(g_voxh + (size_t)vr0 * 256 + c) =
                    make_float2(acc2[mt][nt][0], acc2[mt][nt][1]);
            if (vr1 < V)
                *(float2*)(g_voxh + (size_t)vr1 * 256 + c) =
                    make_float2(acc2[mt][nt][2], acc2[mt][nt][3]);
        }
    }
}

// ---------------------------------------------------------------------------
// Output GEMM (bf16): last-iteration barrier removed
// ---------------------------------------------------------------------------
template <int KC, int NT>
__global__ __launch_bounds__(256, 2) void gemm_out_bf16(
    const float* __restrict__ A, const __nv_bfloat16* __restrict__ Wimg,
    const float* __restrict__ bias, float* __restrict__ out, int M)
{
    const int K = KC * 32;
    const int AST = K / 2 + 4;
    const int NCOL = NT * 32;
    const int BCH = NCOL * 20;
    const int BCH4 = NCOL * 5;
    extern __shared__ uint32_t su[];
    uint32_t* sA32 = su;
    uint32_t* sB32 = su + 64 * AST;
    uint32_t sAu = smem_u32(sA32);
    uint32_t sBu = smem_u32(sB32);
    const uint32_t bufu[2] = {sBu, sBu + (uint32_t)BCH * 4u};

    int t = threadIdx.x;
    int lane = t & 31, wid = t >> 5;
    int g = lane >> 2, t4 = lane & 3;
    int wm = wid & 1, wn = wid >> 1;
    int row0 = blockIdx.x * 64;

    uint32_t aA[2];
#pragma unroll
    for (int mt = 0; mt < 2; mt++)
        aA[mt] = sAu + (uint32_t)(((wm * 32 + mt * 16 + (lane & 15)) * AST + (lane >> 4) * 4) * 4);
    uint32_t bBrel[NT / 2];
    {
        int mat = lane >> 3;
        int nt_off = (mat >> 1) * 8, half = mat & 1;
#pragma unroll
        for (int nt2 = 0; nt2 < NT / 2; nt2++) {
            int row = wn * (NT * 8) + nt2 * 16 + nt_off + (lane & 7);
            bBrel[nt2] = (uint32_t)((row * 20 + half * 4) * 4);
        }
    }

#pragma unroll
    for (int i = 0; i < (BCH4 + 255) / 256; i++) {
        int e = t + i * 256;
        if (e < BCH4) cp_async16(bufu[0] + (uint32_t)e * 16u, (const float4*)Wimg + e);
    }
    CP_COMMIT();

    {
        int p = t >> 2, q = t & 3;
        int cp = min(row0 + p, M - 1);
        const float4* src = (const float4*)(A + (size_t)cp * K) + q * (K / 16);
        uint32_t* dst = sA32 + p * AST + q * (K / 8);
#pragma unroll
        for (int j = 0; j < K / 16; j++) {
            float4 v = src[j];
            dst[2 * j]     = pack_bf16(v.x, v.y);
            dst[2 * j + 1] = pack_bf16(v.z, v.w);
        }
    }

    float acc[2][NT][4];
#pragma unroll
    for (int mt = 0; mt < 2; mt++)
#pragma unroll
        for (int nt = 0; nt < NT; nt++)
#pragma unroll
            for (int j = 0; j < 4; j++) acc[mt][nt][j] = 0.f;

    CP_WAIT0();
    __syncthreads();

#pragma unroll 1
    for (int kc = 0; kc < KC; kc++) {
        if (kc < KC - 1) {
            const float4* ws = (const float4*)(Wimg + (size_t)(kc + 1) * NCOL * 40);
#pragma unroll
            for (int i = 0; i < (BCH4 + 255) / 256; i++) {
                int e = t + i * 256;
                if (e < BCH4) cp_async16(bufu[(kc + 1) & 1] + (uint32_t)e * 16u, ws + e);
            }
            CP_COMMIT();
        }
        uint32_t bbase = bufu[kc & 1];
#pragma unroll
        for (int s = 0; s < 2; s++) {
            uint32_t a[2][4];
            ldsm4(a[0][0], a[0][1], a[0][2], a[0][3], aA[0] + (uint32_t)((kc * 16 + s * 8) * 4));
            ldsm4(a[1][0], a[1][1], a[1][2], a[1][3], aA[1] + (uint32_t)((kc * 16 + s * 8) * 4));
            uint32_t b[NT][2];
#pragma unroll
            for (int nt2 = 0; nt2 < NT / 2; nt2++)
                ldsm4(b[2 * nt2][0], b[2 * nt2][1], b[2 * nt2 + 1][0], b[2 * nt2 + 1][1],
                      bbase + bBrel[nt2] + (uint32_t)(s * 32));
#pragma unroll
            for (int nt = 0; nt < NT; nt++)
#pragma unroll
                for (int mt = 0; mt < 2; mt++)
                    mma_bf16(acc[mt][nt], a[mt][0], a[mt][1], a[mt][2], a[mt][3],
                             b[nt][0], b[nt][1]);
        }
        if (kc < KC - 1) {
            CP_WAIT0();
            __syncthreads();
        }
    }

#pragma unroll
    for (int mt = 0; mt < 2; mt++) {
        int lr = wm * 32 + mt * 16 + g;
        int r0 = row0 + lr, r1 = r0 + 8;
#pragma unroll
        for (int nt = 0; nt < NT; nt++) {
            int c = wn * (NT * 8) + nt * 8 + 2 * t4;
            float bc0 = __ldg(bias + c), bc1 = __ldg(bias + c + 1);
            if (r0 < M)
                *(float2*)(out + (size_t)r0 * NCOL + c) =
                    make_float2(fmaxf(acc[mt][nt][0] + bc0, 0.f), fmaxf(acc[mt][nt][1] + bc1, 0.f));
            if (r1 < M)
                *(float2*)(out + (size_t)r1 * NCOL + c) =
                    make_float2(fmaxf(acc[mt][nt][2] + bc0, 0.f), fmaxf(acc[mt][nt][3] + bc1, 0.f));
        }
    }
}

// ---------------------------------------------------------------------------
// Stage C v6 (R14 + last-iteration barrier removed in GEMM2)
// ---------------------------------------------------------------------------
#define SC4_A_U32   (64 * 132)
#define SC4_B_U32   (2 * 5120)
#define SC4_SMEM    ((SC4_A_U32 + SC4_B_U32 + 64) * 4)

__device__ __forceinline__ void ldBb_async(const __nv_bfloat16* __restrict__ ws,
                                           uint32_t dstu, int t) {
#pragma unroll
    for (int i = 0; i < 5; i++) {
        int e = t + i * 256;
        cp_async16(dstu + (uint32_t)e * 16u, (const float4*)ws + e);
    }
}

__global__ __launch_bounds__(256, 2) void stage_c_bf16(
    const int* __restrict__ vidx, int n,
    const float* __restrict__ b3, const float* __restrict__ b4)
{
    extern __shared__ uint32_t su[];
    uint32_t* sA32 = su;
    uint32_t* sB32 = su + SC4_A_U32;
    int* svx = (int*)(su + SC4_A_U32 + SC4_B_U32);
    uint32_t sAu = smem_u32(sA32);
    uint32_t sBu = smem_u32(sB32);
    const uint32_t bufu[2] = {sBu, sBu + 5120u * 4u};

    int t = threadIdx.x;
    int lane = t & 31, wid = t >> 5;
    int g = lane >> 2, t4 = lane & 3;
    int wm = wid & 1, wn = wid >> 1;
    int row0 = blockIdx.x * 64;

    uint32_t aA[2];
#pragma unroll
    for (int mt = 0; mt < 2; mt++)
        aA[mt] = sAu + (uint32_t)(((wm * 32 + mt * 16 + (lane & 15)) * 132 + (lane >> 4) * 4) * 4);
    uint32_t bBrel[4];
    {
        int mat = lane >> 3;
        int nt_off = (mat >> 1) * 8, half = mat & 1;
#pragma unroll
        for (int nt2 = 0; nt2 < 4; nt2++) {
            int row = wn * 64 + nt2 * 16 + nt_off + (lane & 7);
            bBrel[nt2] = (uint32_t)((row * 20 + half * 4) * 4);
        }
    }

    ldBb_async(g_w3bot, bufu[0], t);
    CP_COMMIT();

    {
        int p = t >> 2, q = t & 3;
        int pt = row0 + p;
        int cp = min(pt, n - 1);
        if (q == 0) svx[p] = vidx[cp];
        const uint4* src = (const uint4*)(g_pf2b + (size_t)cp * 128) + q * 4;
        uint4* dst = (uint4*)(sA32 + p * 132) + q * 4;
#pragma unroll
        for (int j = 0; j < 4; j++) dst[j] = src[j];
    }

    float acc[2][8][4];
#pragma unroll
    for (int mt = 0; mt < 2; mt++)
#pragma unroll
        for (int nt = 0; nt < 8; nt++)
#pragma unroll
            for (int j = 0; j < 4; j++) acc[mt][nt][j] = 0.f;

    CP_WAIT0();
    __syncthreads();

    // ---- GEMM1: pf2 @ w3_bot (4 chunks) ----
#pragma unroll 1
    for (int kc = 0; kc < 4; kc++) {
        if (kc < 3) {
            ldBb_async(g_w3bot + (kc + 1) * 10240, bufu[(kc + 1) & 1], t);
        } else {
            ldBb_async(g_w4b, bufu[0], t);
        }
        CP_COMMIT();
        uint32_t bbase = bufu[kc & 1];
#pragma unroll
        for (int s = 0; s < 2; s++) {
            uint32_t a[2][4];
            ldsm4(a[0][0], a[0][1], a[0][2], a[0][3], aA[0] + (uint32_t)((kc * 16 + s * 8) * 4));
            ldsm4(a[1][0], a[1][1], a[1][2], a[1][3], aA[1] + (uint32_t)((kc * 16 + s * 8) * 4));
            uint32_t b[8][2];
#pragma unroll
            for (int nt2 = 0; nt2 < 4; nt2++)
                ldsm4(b[2 * nt2][0], b[2 * nt2][1], b[2 * nt2 + 1][0], b[2 * nt2 + 1][1],
                      bbase + bBrel[nt2] + (uint32_t)(s * 32));
#pragma unroll
            for (int nt = 0; nt < 8; nt++)
#pragma unroll
                for (int mt = 0; mt < 2; mt++)
                    mma_bf16(acc[mt][nt], a[mt][0], a[mt][1], a[mt][2], a[mt][3],
                             b[nt][0], b[nt][1]);
        }
        CP_WAIT0();
        __syncthreads();
    }

    // epilogue1: h = relu(acc + voxh[vr] + b3) -> sA (bf16)
#pragma unroll
    for (int mt = 0; mt < 2; mt++) {
        int r = wm * 32 + mt * 16 + g;
        const float* vh0 = g_voxh + (size_t)svx[r] * 256;
        const float* vh1 = g_voxh + (size_t)svx[r + 8] * 256;
#pragma unroll
        for (int nt = 0; nt < 8; nt++) {
            int c = wn * 64 + nt * 8 + 2 * t4;
            float bc0 = __ldg(b3 + c), bc1 = __ldg(b3 + c + 1);
            float2 h0v = *(const float2*)(vh0 + c);
            float2 h1v = *(const float2*)(vh1 + c);
            float h0 = fmaxf(acc[mt][nt][0] + h0v.x + bc0, 0.f);
            float h1 = fmaxf(acc[mt][nt][1] + h0v.y + bc1, 0.f);
            float h2 = fmaxf(acc[mt][nt][2] + h1v.x + bc0, 0.f);
            float h3 = fmaxf(acc[mt][nt][3] + h1v.y + bc1, 0.f);
            sA32[r * 132 + (c >> 1)]       = pack_bf16(h0, h1);
            sA32[(r + 8) * 132 + (c >> 1)] = pack_bf16(h2, h3);
            acc[mt][nt][0] = 0.f; acc[mt][nt][1] = 0.f;
            acc[mt][nt][2] = 0.f; acc[mt][nt][3] = 0.f;
        }
    }
    __syncthreads();

    // ---- GEMM2: h @ w4 (8 chunks) ----
#pragma unroll 1
    for (int kc = 0; kc < 8; kc++) {
        if (kc < 7) {
            ldBb_async(g_w4b + (kc + 1) * 10240, bufu[(kc + 1) & 1], t);
            CP_COMMIT();
        }
        uint32_t bbase = bufu[kc & 1];
#pragma unroll
        for (int s = 0; s < 2; s++) {
            uint32_t a[2][4];
            ldsm4(a[0][0], a[0][1], a[0][2], a[0][3], aA[0] + (uint32_t)((kc * 16 + s * 8) * 4));
            ldsm4(a[1][0], a[1][1], a[1][2], a[1][3], aA[1] + (uint32_t)((kc * 16 + s * 8) * 4));
            uint32_t b[8][2];
#pragma unroll
            for (int nt2 = 0; nt2 < 4; nt2++)
                ldsm4(b[2 * nt2][0], b[2 * nt2][1], b[2 * nt2 + 1][0], b[2 * nt2 + 1][1],
                      bbase + bBrel[nt2] + (uint32_t)(s * 32));
#pragma unroll
            for (int nt = 0; nt < 8; nt++)
#pragma unroll
                for (int mt = 0; mt < 2; mt++)
                    mma_bf16(acc[mt][nt], a[mt][0], a[mt][1], a[mt][2], a[mt][3],
                             b[nt][0], b[nt][1]);
        }
        if (kc < 7) {
            CP_WAIT0();
            __syncthreads();
        }
    }

    // epilogue2: pf5 = relu(acc + b4) -> atomicMax scatter into g_vox2
#pragma unroll
    for (int mt = 0; mt < 2; mt++) {
        int lr = wm * 32 + mt * 16 + g;
        int pt0 = row0 + lr, pt1 = pt0 + 8;
        int vr0 = svx[lr], vr1 = svx[lr + 8];
        bool ok0 = pt0 < n, ok1 = pt1 < n;
        float* d0 = g_vox2 + (size_t)vr0 * 256;
        float* d1 = g_vox2 + (size_t)vr1 * 256;
#pragma unroll
        for (int nt = 0; nt < 8; nt++) {
            int c = wn * 64 + nt * 8 + 2 * t4;
            float bc0 = __ldg(b4 + c), bc1 = __ldg(b4 + c + 1);
            if (ok0) {
                amax_pos(d0 + c,     acc[mt][nt][0] + bc0);
                amax_pos(d0 + c + 1, acc[mt][nt][1] + bc1);
            }
            if (ok1) {
                amax_pos(d1 + c,     acc[mt][nt][2] + bc0);
                amax_pos(d1 + c + 1, acc[mt][nt][3] + bc1);
            }
        }
    }
}

// ---------------------------------------------------------------------------
extern "C" void kernel_launch(void* const* d_in, const int* in_sizes, int n_in,
                              void* d_out, int out_size)
{
    const float* inp  = (const float*)d_in[0];
    const int*   vidx = (const int*)d_in[1];
    int base = (n_in >= 23) ? 3 : 2;
    const float* w1x = (const float*)d_in[base + 0];
    const float* b1x = (const float*)d_in[base + 1];
    const float* w2x = (const float*)d_in[base + 2];
    const float* b2x = (const float*)d_in[base + 3];
    const float* w1r = (const float*)d_in[base + 4];
    const float* b1r = (const float*)d_in[base + 5];
    const float* w2r = (const float*)d_in[base + 6];
    const float* b2r = (const float*)d_in[base + 7];
    const float* wax = (const float*)d_in[base + 8];
    const float* bax = (const float*)d_in[base + 9];
    const float* war = (const float*)d_in[base + 10];
    const float* bar = (const float*)d_in[base + 11];
    const float* wv1 = (const float*)d_in[base + 12];
    const float* bv1 = (const float*)d_in[base + 13];
    const float* w3  = (const float*)d_in[base + 14];
    const float* b3  = (const float*)d_in[base + 15];
    const float* w4  = (const float*)d_in[base + 16];
    const float* b4  = (const float*)d_in[base + 17];
    const float* wv2 = (const float*)d_in[base + 18];
    const float* bv2 = (const float*)d_in[base + 19];

    int n = in_sizes[0] / 6;
    int V = out_size / 256;

    const int GO_SMEM = (64 * 132 + 2 * 5120 + 64) * 4;

    auto kOut = gemm_out_bf16<8, 8>;

    cudaFuncSetAttribute(stage_a_mma, cudaFuncAttributeMaxDynamicSharedMemorySize, SAM_SMEM);
    cudaFuncSetAttribute(stage_c_bf16, cudaFuncAttributeMaxDynamicSharedMemorySize, SC4_SMEM);
    cudaFuncSetAttribute(fused_vox, cudaFuncAttributeMaxDynamicSharedMemorySize, FV_SMEM);
    cudaFuncSetAttribute(kOut, cudaFuncAttributeMaxDynamicSharedMemorySize, GO_SMEM);

    float *p_vox2;
    __nv_bfloat16 *p_wvb;
    cudaGetSymbolAddress((void**)&p_vox2, g_vox2);
    cudaGetSymbolAddress((void**)&p_wvb, g_wvb);

    init_all<<<1480, 256>>>(w3, w4, wv2, wv1, V * 128, V * 256);

    stage_a_mma<<<(n + 127) / 128, SAM_THREADS, SAM_SMEM>>>(
        inp, vidx, n, w1x, b1x, w2x, b2x, w1r, b1r, w2r, b2r, wax, bax, war, bar);

    fused_vox<<<(V + 63) / 64, 256, FV_SMEM>>>(bv1, V);

    stage_c_bf16<<<(n + 63) / 64, 256, SC4_SMEM>>>(vidx, n, b3, b4);

    kOut<<<(V + 63) / 64, 256, GO_SMEM>>>(p_vox2, p_wvb, bv2, (float*)d_out, V);
}

// round 17
// speedup vs baseline: 1.0759x; 1.0013x over previous
#include <cuda_runtime.h>
#include <cuda_bf16.h>
#include <cstdint>
#include <math.h>

#define MAXN 500000
#define MAXV 50000

// ---- scratch (static __device__ arrays; allocation-free) ----
__device__ __align__(128) __nv_bfloat16 g_pf2b[(size_t)MAXN * 128];   // pf2 bf16
__device__ __align__(128) float g_vox[(size_t)MAXV * 128];
__device__ __align__(128) __nv_bfloat16 g_voxfb[(size_t)MAXV * 128];  // voxf bf16
__device__ __align__(128) float g_voxh[(size_t)MAXV * 256];           // voxf @ w3_top
__device__ __align__(128) float g_vox2[(size_t)MAXV * 256];
__device__ __align__(128) __nv_bfloat16 g_w3top[40960];  // w3 rows 0..127  [4][256][40]
__device__ __align__(128) __nv_bfloat16 g_w3bot[40960];  // w3 rows 128..255
__device__ __align__(128) __nv_bfloat16 g_w4b[81920];    // w4 [8][256][40]
__device__ __align__(128) __nv_bfloat16 g_wvb[81920];    // wv2
__device__ __align__(128) __nv_bfloat16 g_wv1b[20480];   // wv1 [4][128][40]

__device__ __forceinline__ void amax_pos(float* addr, float v) {
    if (v > 0.f) atomicMax((int*)addr, __float_as_int(v));
}

__device__ __forceinline__ uint32_t f2tf32(float f) {
    uint32_t r;
    asm("cvt.rna.tf32.f32 %0, %1;" : "=r"(r) : "f"(f));
    return r;
}
__device__ __forceinline__ float tf32f(float f) { return __uint_as_float(f2tf32(f)); }

__device__ __forceinline__ uint32_t pack_bf16(float a, float b) {
    __nv_bfloat162 h = __floats2bfloat162_rn(a, b);
    uint32_t r;
    memcpy(&r, &h, 4);
    return r;
}

__device__ __forceinline__ uint32_t smem_u32(const void* p) {
    return (uint32_t)__cvta_generic_to_shared(p);
}
__device__ __forceinline__ void cp_async16(uint32_t dst, const void* src) {
    asm volatile("cp.async.cg.shared.global [%0], [%1], 16;" :: "r"(dst), "l"(src));
}
#define CP_COMMIT() asm volatile("cp.async.commit_group;" ::: "memory")
#define CP_WAIT0()  asm volatile("cp.async.wait_group 0;" ::: "memory")

__device__ __forceinline__ void ldsm4(uint32_t& r0, uint32_t& r1, uint32_t& r2,
                                      uint32_t& r3, uint32_t addr) {
    asm volatile("ldmatrix.sync.aligned.m8n8.x4.shared.b16 {%0,%1,%2,%3}, [%4];"
                 : "=r"(r0), "=r"(r1), "=r"(r2), "=r"(r3) : "r"(addr));
}

__device__ __forceinline__ void mma_bf16(float acc[4], uint32_t a0, uint32_t a1,
                                         uint32_t a2, uint32_t a3, uint32_t b0, uint32_t b1) {
    asm volatile(
        "mma.sync.aligned.m16n8k16.row.col.f32.bf16.bf16.f32 "
        "{%0,%1,%2,%3},{%4,%5,%6,%7},{%8,%9},{%0,%1,%2,%3};"
        : "+f"(acc[0]), "+f"(acc[1]), "+f"(acc[2]), "+f"(acc[3])
        : "r"(a0), "r"(a1), "r"(a2), "r"(a3), "r"(b0), "r"(b1));
}

__device__ __forceinline__ void mma_tf32(float acc[4], uint32_t a0, uint32_t a1,
                                         uint32_t a2, uint32_t a3, uint32_t b0, uint32_t b1) {
    asm volatile(
        "mma.sync.aligned.m16n8k8.row.col.f32.tf32.tf32.f32 "
        "{%0,%1,%2,%3},{%4,%5,%6,%7},{%8,%9},{%0,%1,%2,%3};"
        : "+f"(acc[0]), "+f"(acc[1]), "+f"(acc[2]), "+f"(acc[3])
        : "r"(a0), "r"(a1), "r"(a2), "r"(a3), "r"(b0), "r"(b1));
}

// ---------------------------------------------------------------------------
// zero_vox: only g_vox (needed before stage_a's atomics)
// ---------------------------------------------------------------------------
__global__ void zero_vox(int na) {
    int i = blockIdx.x * blockDim.x + threadIdx.x;
    int stride = gridDim.x * blockDim.x;
    for (int j = i; j < na; j += stride) g_vox[j] = 0.f;
}

// side_init: weight-image prep + zero g_vox2 (only needed before fused_vox /
// stage_c) — runs on a side stream overlapped with stage_a.
// ---------------------------------------------------------------------------
__device__ __forceinline__ void blk_one(const float* __restrict__ w,
                                        __nv_bfloat16* __restrict__ d, int j, int NCOL) {
    int per = NCOL * 40;
    int kc = j / per, rem = j % per, nn = rem / 40, kl = rem % 40;
    float v = (kl < 32) ? w[(size_t)(kc * 32 + kl) * NCOL + nn] : 0.f;
    d[j] = __float2bfloat16(v);
}

__global__ void side_init(const float* __restrict__ w3, const float* __restrict__ w4,
                          const float* __restrict__ wv2, const float* __restrict__ wv1,
                          int nb) {
    int i = blockIdx.x * blockDim.x + threadIdx.x;
    int stride = gridDim.x * blockDim.x;
    for (int j = i; j < nb; j += stride) g_vox2[j] = 0.f;
    for (int j = i; j < 266240; j += stride) {
        if (j < 40960) blk_one(w3, g_w3top, j, 256);
        else if (j < 81920) blk_one(w3 + 128 * 256, g_w3bot, j - 40960, 256);
        else if (j < 163840) blk_one(w4, g_w4b, j - 81920, 256);
        else if (j < 245760) blk_one(wv2, g_wvb, j - 163840, 256);
        else blk_one(wv1, g_wv1b, j - 245760, 128);
    }
}

// ---------------------------------------------------------------------------
// warp micro-GEMM helper: [16x64]@[64x32] tf32, A stride 68, B stride 40
// ---------------------------------------------------------------------------
__device__ __forceinline__ void gemm64x32(const float* __restrict__ As,
                                          const float* __restrict__ Bt,
                                          int wr, int g, int t4, float acc[4][4]) {
#pragma unroll
    for (int k8 = 0; k8 < 8; k8++) {
        const float* ap = As + (wr + g) * 68 + k8 * 8 + t4;
        uint32_t a0 = __float_as_uint(ap[0]);
        uint32_t a1 = __float_as_uint(ap[8 * 68]);
        uint32_t a2 = __float_as_uint(ap[4]);
        uint32_t a3 = __float_as_uint(ap[8 * 68 + 4]);
#pragma unroll
        for (int nt = 0; nt < 4; nt++) {
            const float* bp = Bt + (k8 * 8 + t4) * 40 + nt * 8 + g;
            uint32_t b0 = __float_as_uint(bp[0]);
            uint32_t b1 = __float_as_uint(bp[4 * 40]);
            mma_tf32(acc[nt], a0, a1, a2, a3, b0, b1);
        }
    }
}

// ---------------------------------------------------------------------------
// Stage A via mma.sync tf32 (R14/R16 known-good: sC removed, 2 CTA/SM)
// ---------------------------------------------------------------------------
#define SAM_THREADS 256
#define SAM_SMEM ((512 + 10240 + 128 * 68 + 128) * 4)

__global__ __launch_bounds__(SAM_THREADS, 2) void stage_a_mma(
    const float* __restrict__ inp, const int* __restrict__ vidx, int n,
    const float* __restrict__ w1x, const float* __restrict__ b1x,
    const float* __restrict__ w2x, const float* __restrict__ b2x,
    const float* __restrict__ w1r, const float* __restrict__ b1r,
    const float* __restrict__ w2r, const float* __restrict__ b2r,
    const float* __restrict__ wax, const float* __restrict__ bax,
    const float* __restrict__ war, const float* __restrict__ bar)
{
    extern __shared__ float sm[];
    float* sW = sm;                      // 512
    float* sB = sm + 512;                // 4 x 2560
    float* sA = sm + 10752;              // [128][68]  (hidden, then comb)
    int*   svx = (int*)(sm + 10752 + 128 * 68);

    int t = threadIdx.x;
    int lane = t & 31, w = t >> 5;
    int g = lane >> 2, t4 = lane & 3;
    int wr = 16 * w;
    int row0 = blockIdx.x * 128;

    for (int i = t; i < 192; i += SAM_THREADS) { sW[i] = w1x[i]; sW[256 + i] = w1r[i]; }
    for (int i = t; i < 64; i += SAM_THREADS)  { sW[192 + i] = b1x[i]; sW[448 + i] = b1r[i]; }
    {
        const float* wsrc[4] = {w2x, w2r, wax, war};
#pragma unroll
        for (int a = 0; a < 4; a++) {
            float* dst = sB + a * 2560;
            const float* s = wsrc[a];
            for (int i = t; i < 2048; i += SAM_THREADS) {
                int k = i >> 5, c = i & 31;
                dst[k * 40 + c] = __uint_as_float(f2tf32(s[i]));
            }
        }
    }
    __syncthreads();

    int p = t >> 1, half = t & 1;
    int cp = min(row0 + p, n - 1);
    if (half == 0) svx[p] = vidx[cp];
    float i0 = inp[(size_t)cp * 6 + 0], i1 = inp[(size_t)cp * 6 + 1], i2 = inp[(size_t)cp * 6 + 2];
    float i3 = inp[(size_t)cp * 6 + 3], i4 = inp[(size_t)cp * 6 + 4], i5 = inp[(size_t)cp * 6 + 5];

    // layer1 xyz -> sA
    {
        const float* W = sW; const float* B = sW + 192;
        int ob = half * 32;
#pragma unroll 8
        for (int o = 0; o < 32; o++) {
            int oo = ob + o;
            float a = B[oo] + i0 * W[oo] + i1 * W[64 + oo] + i2 * W[128 + oo];
            sA[p * 68 + oo] = tf32f(fmaxf(a, 0.f));
        }
    }
    __syncwarp();

    // GEMM fx
    float fx[4][4];
#pragma unroll
    for (int nt = 0; nt < 4; nt++)
#pragma unroll
        for (int j = 0; j < 4; j++) fx[nt][j] = 0.f;
    gemm64x32(sA, sB, wr, g, t4, fx);
    __syncwarp();

    // bias+relu fx (kept in regs); layer1 rgb -> sA (overwrite)
#pragma unroll
    for (int nt = 0; nt < 4; nt++) {
        int c = nt * 8 + 2 * t4;
        float bc0 = __ldg(b2x + c), bc1 = __ldg(b2x + c + 1);
        fx[nt][0] = fmaxf(fx[nt][0] + bc0, 0.f);
        fx[nt][1] = fmaxf(fx[nt][1] + bc1, 0.f);
        fx[nt][2] = fmaxf(fx[nt][2] + bc0, 0.f);
        fx[nt][3] = fmaxf(fx[nt][3] + bc1, 0.f);
    }
    {
        const float* W = sW + 256; const float* B = sW + 448;
        int ob = half * 32;
#pragma unroll 8
        for (int o = 0; o < 32; o++) {
            int oo = ob + o;
            float a = B[oo] + i3 * W[oo] + i4 * W[64 + oo] + i5 * W[128 + oo];
            sA[p * 68 + oo] = tf32f(fmaxf(a, 0.f));
        }
    }
    __syncwarp();

    // GEMM fr
    float fr[4][4];
#pragma unroll
    for (int nt = 0; nt < 4; nt++)
#pragma unroll
        for (int j = 0; j < 4; j++) fr[nt][j] = 0.f;
    gemm64x32(sA, sB + 2560, wr, g, t4, fr);
    __syncwarp();

    // write comb = [fx, fr] into sA (tf32), overwriting the dead hidden tile
#pragma unroll
    for (int nt = 0; nt < 4; nt++) {
        int c = nt * 8 + 2 * t4;
        float bc0 = __ldg(b2r + c), bc1 = __ldg(b2r + c + 1);
        fr[nt][0] = fmaxf(fr[nt][0] + bc0, 0.f);
        fr[nt][1] = fmaxf(fr[nt][1] + bc1, 0.f);
        fr[nt][2] = fmaxf(fr[nt][2] + bc0, 0.f);
        fr[nt][3] = fmaxf(fr[nt][3] + bc1, 0.f);
        int r = wr + g;
        *(float2*)(sA + r * 68 + c) = make_float2(tf32f(fx[nt][0]), tf32f(fx[nt][1]));
        *(float2*)(sA + (r + 8) * 68 + c) = make_float2(tf32f(fx[nt][2]), tf32f(fx[nt][3]));
        *(float2*)(sA + r * 68 + 32 + c) = make_float2(tf32f(fr[nt][0]), tf32f(fr[nt][1]));
        *(float2*)(sA + (r + 8) * 68 + 32 + c) = make_float2(tf32f(fr[nt][2]), tf32f(fr[nt][3]));
    }
    __syncwarp();

    // attention GEMMs (comb K=64)
    float ax[4][4], ar[4][4];
#pragma unroll
    for (int nt = 0; nt < 4; nt++)
#pragma unroll
        for (int j = 0; j < 4; j++) { ax[nt][j] = 0.f; ar[nt][j] = 0.f; }
    gemm64x32(sA, sB + 2 * 2560, wr, g, t4, ax);
    gemm64x32(sA, sB + 3 * 2560, wr, g, t4, ar);

#pragma unroll
    for (int h2 = 0; h2 < 2; h2++) {
        int r = wr + g + 8 * h2;
        int pt = row0 + r;
        if (pt < n) {
            int vr = svx[r];
            uint32_t* pfr = (uint32_t*)(g_pf2b + (size_t)pt * 128);
            float* vxr = g_vox + (size_t)vr * 128;
#pragma unroll
            for (int nt = 0; nt < 4; nt++) {
                int c = nt * 8 + 2 * t4;
                int j0 = 2 * h2, j1 = 2 * h2 + 1;
                float axa = ax[nt][j0] + __ldg(bax + c);
                float axb = ax[nt][j1] + __ldg(bax + c + 1);
                float ara = ar[nt][j0] + __ldg(bar + c);
                float arb = ar[nt][j1] + __ldg(bar + c + 1);
                float sxa = 1.f / (1.f + __expf(-axa));
                float sxb = 1.f / (1.f + __expf(-axb));
                float sra = 1.f / (1.f + __expf(-ara));
                float srb = 1.f / (1.f + __expf(-arb));
                float fxa = fx[nt][j0], fxb = fx[nt][j1];
                float fra = fr[nt][j0], frb = fr[nt][j1];
                float v1a = fxa * sxa, v1b = fxb * sxb;
                float v3a = fra * sra, v3b = frb * srb;
                int cw = c >> 1;
                pfr[cw]      = pack_bf16(fxa, fxb);
                pfr[16 + cw] = pack_bf16(v1a, v1b);
                pfr[32 + cw] = pack_bf16(fra, frb);
                pfr[48 + cw] = pack_bf16(v3a, v3b);
                amax_pos(vxr + c, fxa);        amax_pos(vxr + c + 1, fxb);
                amax_pos(vxr + 32 + c, v1a);   amax_pos(vxr + 33 + c, v1b);
                amax_pos(vxr + 64 + c, fra);   amax_pos(vxr + 65 + c, frb);
                amax_pos(vxr + 96 + c, v3a);   amax_pos(vxr + 97 + c, v3b);
            }
        }
    }
}

// ---------------------------------------------------------------------------
// Fused voxel kernel (unchanged from R16)
// ---------------------------------------------------------------------------
#define FV_A_U32  (64 * 68)
#define FV_B_U32  (2 * 5120)
#define FV_SMEM   ((FV_A_U32 + FV_B_U32 + 64) * 4)

__global__ __launch_bounds__(256, 2) void fused_vox(
    const float* __restrict__ bv1, int V)
{
    extern __shared__ uint32_t su[];
    uint32_t* sA32 = su;
    uint32_t* sB32 = su + FV_A_U32;
    uint32_t sAu = smem_u32(sA32);
    uint32_t sBu = smem_u32(sB32);
    const uint32_t bufu[2] = {sBu, sBu + 5120u * 4u};

    int t = threadIdx.x;
    int lane = t & 31, wid = t >> 5;
    int g = lane >> 2, t4 = lane & 3;
    int wm = wid & 1, wn = wid >> 1;
    int row0 = blockIdx.x * 64;

    uint32_t aA[2];
#pragma unroll
    for (int mt = 0; mt < 2; mt++)
        aA[mt] = sAu + (uint32_t)(((wm * 32 + mt * 16 + (lane & 15)) * 68 + (lane >> 4) * 4) * 4);
    uint32_t bRel1[2], bRel2[4];
    {
        int mat = lane >> 3;
        int nt_off = (mat >> 1) * 8, hf = mat & 1;
#pragma unroll
        for (int nt2 = 0; nt2 < 2; nt2++) {
            int row = wn * 32 + nt2 * 16 + nt_off + (lane & 7);
            bRel1[nt2] = (uint32_t)((row * 20 + hf * 4) * 4);
        }
#pragma unroll
        for (int nt2 = 0; nt2 < 4; nt2++) {
            int row = wn * 64 + nt2 * 16 + nt_off + (lane & 7);
            bRel2[nt2] = (uint32_t)((row * 20 + hf * 4) * 4);
        }
    }

#pragma unroll
    for (int i = 0; i < 3; i++) {
        int e = t + i * 256;
        if (e < 640) cp_async16(bufu[0] + (uint32_t)e * 16u, (const float4*)g_wv1b + e);
    }
    CP_COMMIT();

    {
        int p = t >> 2, q = t & 3;
        int cp = min(row0 + p, V - 1);
        const float4* src = (const float4*)(g_vox + (size_t)cp * 128) + q * 8;
        uint32_t* dst = sA32 + p * 68 + q * 16;
#pragma unroll
        for (int j = 0; j < 8; j++) {
            float4 v = src[j];
            dst[2 * j]     = pack_bf16(v.x, v.y);
            dst[2 * j + 1] = pack_bf16(v.z, v.w);
        }
    }

    float acc1[2][4][4];
#pragma unroll
    for (int mt = 0; mt < 2; mt++)
#pragma unroll
        for (int nt = 0; nt < 4; nt++)
#pragma unroll
            for (int j = 0; j < 4; j++) acc1[mt][nt][j] = 0.f;

    CP_WAIT0();
    __syncthreads();

#pragma unroll 1
    for (int kc = 0; kc < 4; kc++) {
        if (kc < 3) {
            const float4* ws = (const float4*)(g_wv1b + (kc + 1) * 5120);
#pragma unroll
            for (int i = 0; i < 3; i++) {
                int e = t + i * 256;
                if (e < 640) cp_async16(bufu[(kc + 1) & 1] + (uint32_t)e * 16u, ws + e);
            }
        } else {
            const float4* ws = (const float4*)g_w3top;
#pragma unroll
            for (int i = 0; i < 5; i++) {
                int e = t + i * 256;
                cp_async16(bufu[0] + (uint32_t)e * 16u, ws + e);
            }
        }
        CP_COMMIT();
        uint32_t bbase = bufu[kc & 1];
#pragma unroll
        for (int s = 0; s < 2; s++) {
            uint32_t a[2][4];
            ldsm4(a[0][0], a[0][1], a[0][2], a[0][3], aA[0] + (uint32_t)((kc * 16 + s * 8) * 4));
            ldsm4(a[1][0], a[1][1], a[1][2], a[1][3], aA[1] + (uint32_t)((kc * 16 + s * 8) * 4));
            uint32_t b[4][2];
#pragma unroll
            for (int nt2 = 0; nt2 < 2; nt2++)
                ldsm4(b[2 * nt2][0], b[2 * nt2][1], b[2 * nt2 + 1][0], b[2 * nt2 + 1][1],
                      bbase + bRel1[nt2] + (uint32_t)(s * 32));
#pragma unroll
            for (int nt = 0; nt < 4; nt++)
#pragma unroll
                for (int mt = 0; mt < 2; mt++)
                    mma_bf16(acc1[mt][nt], a[mt][0], a[mt][1], a[mt][2], a[mt][3],
                             b[nt][0], b[nt][1]);
        }
        CP_WAIT0();
        __syncthreads();
    }

#pragma unroll
    for (int mt = 0; mt < 2; mt++) {
        int r = wm * 32 + mt * 16 + g;
        int vr0 = row0 + r, vr1 = row0 + r + 8;
        uint32_t* o0 = (uint32_t*)(g_voxfb + (size_t)vr0 * 128);
        uint32_t* o1 = (uint32_t*)(g_voxfb + (size_t)vr1 * 128);
#pragma unroll
        for (int nt = 0; nt < 4; nt++) {
            int c = wn * 32 + nt * 8 + 2 * t4;
            float bc0 = __ldg(bv1 + c), bc1 = __ldg(bv1 + c + 1);
            float h0 = fmaxf(acc1[mt][nt][0] + bc0, 0.f);
            float h1 = fmaxf(acc1[mt][nt][1] + bc1, 0.f);
            float h2 = fmaxf(acc1[mt][nt][2] + bc0, 0.f);
            float h3 = fmaxf(acc1[mt][nt][3] + bc1, 0.f);
            uint32_t p01 = pack_bf16(h0, h1), p23 = pack_bf16(h2, h3);
            sA32[r * 68 + (c >> 1)]       = p01;
            sA32[(r + 8) * 68 + (c >> 1)] = p23;
            if (vr0 < V) o0[c >> 1] = p01;
            if (vr1 < V) o1[c >> 1] = p23;
        }
    }
    __syncthreads();

    float acc2[2][8][4];
#pragma unroll
    for (int mt = 0; mt < 2; mt++)
#pragma unroll
        for (int nt = 0; nt < 8; nt++)
#pragma unroll
            for (int j = 0; j < 4; j++) acc2[mt][nt][j] = 0.f;

#pragma unroll 1
    for (int kc = 0; kc < 4; kc++) {
        if (kc < 3) {
            const float4* ws = (const float4*)(g_w3top + (kc + 1) * 10240);
#pragma unroll
            for (int i = 0; i < 5; i++) {
                int e = t + i * 256;
                cp_async16(bufu[(kc + 1) & 1] + (uint32_t)e * 16u, ws + e);
            }
            CP_COMMIT();
        }
        uint32_t bbase = bufu[kc & 1];
#pragma unroll
        for (int s = 0; s < 2; s++) {
            uint32_t a[2][4];
            ldsm4(a[0][0], a[0][1], a[0][2], a[0][3], aA[0] + (uint32_t)((kc * 16 + s * 8) * 4));
            ldsm4(a[1][0], a[1][1], a[1][2], a[1][3], aA[1] + (uint32_t)((kc * 16 + s * 8) * 4));
            uint32_t b[8][2];
#pragma unroll
            for (int nt2 = 0; nt2 < 4; nt2++)
                ldsm4(b[2 * nt2][0], b[2 * nt2][1], b[2 * nt2 + 1][0], b[2 * nt2 + 1][1],
                      bbase + bRel2[nt2] + (uint32_t)(s * 32));
#pragma unroll
            for (int nt = 0; nt < 8; nt++)
#pragma unroll
                for (int mt = 0; mt < 2; mt++)
                    mma_bf16(acc2[mt][nt], a[mt][0], a[mt][1], a[mt][2], a[mt][3],
                             b[nt][0], b[nt][1]);
        }
        if (kc < 3) {
            CP_WAIT0();
            __syncthreads();
        }
    }

#pragma unroll
    for (int mt = 0; mt < 2; mt++) {
        int r = wm * 32 + mt * 16 + g;
        int vr0 = row0 + r, vr1 = vr0 + 8;
#pragma unroll
        for (int nt = 0; nt < 8; nt++) {
            int c = wn * 64 + nt * 8 + 2 * t4;
            if (vr0 < V)
                *(float2*)(g_voxh + (size_t)vr0 * 256 + c) =
                    make_float2(acc2[mt][nt][0], acc2[mt][nt][1]);
            if (vr1 < V)
                *(float2*)(g_voxh + (size_t)vr1 * 256 + c) =
                    make_float2(acc2[mt][nt][2], acc2[mt][nt][3]);
        }
    }
}

// ---------------------------------------------------------------------------
// Output GEMM (bf16, unchanged from R16)
// ---------------------------------------------------------------------------
template <int KC, int NT>
__global__ __launch_bounds__(256, 2) void gemm_out_bf16(
    const float* __restrict__ A, const __nv_bfloat16* __restrict__ Wimg,
    const float* __restrict__ bias, float* __restrict__ out, int M)
{
    const int K = KC * 32;
    const int AST = K / 2 + 4;
    const int NCOL = NT * 32;
    const int BCH = NCOL * 20;
    const int BCH4 = NCOL * 5;
    extern __shared__ uint32_t su[];
    uint32_t* sA32 = su;
    uint32_t* sB32 = su + 64 * AST;
    uint32_t sAu = smem_u32(sA32);
    uint32_t sBu = smem_u32(sB32);
    const uint32_t bufu[2] = {sBu, sBu + (uint32_t)BCH * 4u};

    int t = threadIdx.x;
    int lane = t & 31, wid = t >> 5;
    int g = lane >> 2, t4 = lane & 3;
    int wm = wid & 1, wn = wid >> 1;
    int row0 = blockIdx.x * 64;

    uint32_t aA[2];
#pragma unroll
    for (int mt = 0; mt < 2; mt++)
        aA[mt] = sAu + (uint32_t)(((wm * 32 + mt * 16 + (lane & 15)) * AST + (lane >> 4) * 4) * 4);
    uint32_t bBrel[NT / 2];
    {
        int mat = lane >> 3;
        int nt_off = (mat >> 1) * 8, half = mat & 1;
#pragma unroll
        for (int nt2 = 0; nt2 < NT / 2; nt2++) {
            int row = wn * (NT * 8) + nt2 * 16 + nt_off + (lane & 7);
            bBrel[nt2] = (uint32_t)((row * 20 + half * 4) * 4);
        }
    }

#pragma unroll
    for (int i = 0; i < (BCH4 + 255) / 256; i++) {
        int e = t + i * 256;
        if (e < BCH4) cp_async16(bufu[0] + (uint32_t)e * 16u, (const float4*)Wimg + e);
    }
    CP_COMMIT();

    {
        int p = t >> 2, q = t & 3;
        int cp = min(row0 + p, M - 1);
        const float4* src = (const float4*)(A + (size_t)cp * K) + q * (K / 16);
        uint32_t* dst = sA32 + p * AST + q * (K / 8);
#pragma unroll
        for (int j = 0; j < K / 16; j++) {
            float4 v = src[j];
            dst[2 * j]     = pack_bf16(v.x, v.y);
            dst[2 * j + 1] = pack_bf16(v.z, v.w);
        }
    }

    float acc[2][NT][4];
#pragma unroll
    for (int mt = 0; mt < 2; mt++)
#pragma unroll
        for (int nt = 0; nt < NT; nt++)
#pragma unroll
            for (int j = 0; j < 4; j++) acc[mt][nt][j] = 0.f;

    CP_WAIT0();
    __syncthreads();

#pragma unroll 1
    for (int kc = 0; kc < KC; kc++) {
        if (kc < KC - 1) {
            const float4* ws = (const float4*)(Wimg + (size_t)(kc + 1) * NCOL * 40);
#pragma unroll
            for (int i = 0; i < (BCH4 + 255) / 256; i++) {
                int e = t + i * 256;
                if (e < BCH4) cp_async16(bufu[(kc + 1) & 1] + (uint32_t)e * 16u, ws + e);
            }
            CP_COMMIT();
        }
        uint32_t bbase = bufu[kc & 1];
#pragma unroll
        for (int s = 0; s < 2; s++) {
            uint32_t a[2][4];
            ldsm4(a[0][0], a[0][1], a[0][2], a[0][3], aA[0] + (uint32_t)((kc * 16 + s * 8) * 4));
            ldsm4(a[1][0], a[1][1], a[1][2], a[1][3], aA[1] + (uint32_t)((kc * 16 + s * 8) * 4));
            uint32_t b[NT][2];
#pragma unroll
            for (int nt2 = 0; nt2 < NT / 2; nt2++)
                ldsm4(b[2 * nt2][0], b[2 * nt2][1], b[2 * nt2 + 1][0], b[2 * nt2 + 1][1],
                      bbase + bBrel[nt2] + (uint32_t)(s * 32));
#pragma unroll
            for (int nt = 0; nt < NT; nt++)
#pragma unroll
                for (int mt = 0; mt < 2; mt++)
                    mma_bf16(acc[mt][nt], a[mt][0], a[mt][1], a[mt][2], a[mt][3],
                             b[nt][0], b[nt][1]);
        }
        if (kc < KC - 1) {
            CP_WAIT0();
            __syncthreads();
        }
    }

#pragma unroll
    for (int mt = 0; mt < 2; mt++) {
        int lr = wm * 32 + mt * 16 + g;
        int r0 = row0 + lr, r1 = r0 + 8;
#pragma unroll
        for (int nt = 0; nt < NT; nt++) {
            int c = wn * (NT * 8) + nt * 8 + 2 * t4;
            float bc0 = __ldg(bias + c), bc1 = __ldg(bias + c + 1);
            if (r0 < M)
                *(float2*)(out + (size_t)r0 * NCOL + c) =
                    make_float2(fmaxf(acc[mt][nt][0] + bc0, 0.f), fmaxf(acc[mt][nt][1] + bc1, 0.f));
            if (r1 < M)
                *(float2*)(out + (size_t)r1 * NCOL + c) =
                    make_float2(fmaxf(acc[mt][nt][2] + bc0, 0.f), fmaxf(acc[mt][nt][3] + bc1, 0.f));
        }
    }
}

// ---------------------------------------------------------------------------
// Stage C v6 (unchanged from R16)
// ---------------------------------------------------------------------------
#define SC4_A_U32   (64 * 132)
#define SC4_B_U32   (2 * 5120)
#define SC4_SMEM    ((SC4_A_U32 + SC4_B_U32 + 64) * 4)

__device__ __forceinline__ void ldBb_async(const __nv_bfloat16* __restrict__ ws,
                                           uint32_t dstu, int t) {
#pragma unroll
    for (int i = 0; i < 5; i++) {
        int e = t + i * 256;
        cp_async16(dstu + (uint32_t)e * 16u, (const float4*)ws + e);
    }
}

__global__ __launch_bounds__(256, 2) void stage_c_bf16(
    const int* __restrict__ vidx, int n,
    const float* __restrict__ b3, const float* __restrict__ b4)
{
    extern __shared__ uint32_t su[];
    uint32_t* sA32 = su;
    uint32_t* sB32 = su + SC4_A_U32;
    int* svx = (int*)(su + SC4_A_U32 + SC4_B_U32);
    uint32_t sAu = smem_u32(sA32);
    uint32_t sBu = smem_u32(sB32);
    const uint32_t bufu[2] = {sBu, sBu + 5120u * 4u};

    int t = threadIdx.x;
    int lane = t & 31, wid = t >> 5;
    int g = lane >> 2, t4 = lane & 3;
    int wm = wid & 1, wn = wid >> 1;
    int row0 = blockIdx.x * 64;

    uint32_t aA[2];
#pragma unroll
    for (int mt = 0; mt < 2; mt++)
        aA[mt] = sAu + (uint32_t)(((wm * 32 + mt * 16 + (lane & 15)) * 132 + (lane >> 4) * 4) * 4);
    uint32_t bBrel[4];
    {
        int mat = lane >> 3;
        int nt_off = (mat >> 1) * 8, half = mat & 1;
#pragma unroll
        for (int nt2 = 0; nt2 < 4; nt2++) {
            int row = wn * 64 + nt2 * 16 + nt_off + (lane & 7);
            bBrel[nt2] = (uint32_t)((row * 20 + half * 4) * 4);
        }
    }

    ldBb_async(g_w3bot, bufu[0], t);
    CP_COMMIT();

    {
        int p = t >> 2, q = t & 3;
        int pt = row0 + p;
        int cp = min(pt, n - 1);
        if (q == 0) svx[p] = vidx[cp];
        const uint4* src = (const uint4*)(g_pf2b + (size_t)cp * 128) + q * 4;
        uint4* dst = (uint4*)(sA32 + p * 132) + q * 4;
#pragma unroll
        for (int j = 0; j < 4; j++) dst[j] = src[j];
    }

    float acc[2][8][4];
#pragma unroll
    for (int mt = 0; mt < 2; mt++)
#pragma unroll
        for (int nt = 0; nt < 8; nt++)
#pragma unroll
            for (int j = 0; j < 4; j++) acc[mt][nt][j] = 0.f;

    CP_WAIT0();
    __syncthreads();

    // ---- GEMM1: pf2 @ w3_bot (4 chunks) ----
#pragma unroll 1
    for (int kc = 0; kc < 4; kc++) {
        if (kc < 3) {
            ldBb_async(g_w3bot + (kc + 1) * 10240, bufu[(kc + 1) & 1], t);
        } else {
            ldBb_async(g_w4b, bufu[0], t);
        }
        CP_COMMIT();
        uint32_t bbase = bufu[kc & 1];
#pragma unroll
        for (int s = 0; s < 2; s++) {
            uint32_t a[2][4];
            ldsm4(a[0][0], a[0][1], a[0][2], a[0][3], aA[0] + (uint32_t)((kc * 16 + s * 8) * 4));
            ldsm4(a[1][0], a[1][1], a[1][2], a[1][3], aA[1] + (uint32_t)((kc * 16 + s * 8) * 4));
            uint32_t b[8][2];
#pragma unroll
            for (int nt2 = 0; nt2 < 4; nt2++)
                ldsm4(b[2 * nt2][0], b[2 * nt2][1], b[2 * nt2 + 1][0], b[2 * nt2 + 1][1],
                      bbase + bBrel[nt2] + (uint32_t)(s * 32));
#pragma unroll
            for (int nt = 0; nt < 8; nt++)
#pragma unroll
                for (int mt = 0; mt < 2; mt++)
                    mma_bf16(acc[mt][nt], a[mt][0], a[mt][1], a[mt][2], a[mt][3],
                             b[nt][0], b[nt][1]);
        }
        CP_WAIT0();
        __syncthreads();
    }

    // epilogue1: h = relu(acc + voxh[vr] + b3) -> sA (bf16)
#pragma unroll
    for (int mt = 0; mt < 2; mt++) {
        int r = wm * 32 + mt * 16 + g;
        const float* vh0 = g_voxh + (size_t)svx[r] * 256;
        const float* vh1 = g_voxh + (size_t)svx[r + 8] * 256;
#pragma unroll
        for (int nt = 0; nt < 8; nt++) {
            int c = wn * 64 + nt * 8 + 2 * t4;
            float bc0 = __ldg(b3 + c), bc1 = __ldg(b3 + c + 1);
            float2 h0v = *(const float2*)(vh0 + c);
            float2 h1v = *(const float2*)(vh1 + c);
            float h0 = fmaxf(acc[mt][nt][0] + h0v.x + bc0, 0.f);
            float h1 = fmaxf(acc[mt][nt][1] + h0v.y + bc1, 0.f);
            float h2 = fmaxf(acc[mt][nt][2] + h1v.x + bc0, 0.f);
            float h3 = fmaxf(acc[mt][nt][3] + h1v.y + bc1, 0.f);
            sA32[r * 132 + (c >> 1)]       = pack_bf16(h0, h1);
            sA32[(r + 8) * 132 + (c >> 1)] = pack_bf16(h2, h3);
            acc[mt][nt][0] = 0.f; acc[mt][nt][1] = 0.f;
            acc[mt][nt][2] = 0.f; acc[mt][nt][3] = 0.f;
        }
    }
    __syncthreads();

    // ---- GEMM2: h @ w4 (8 chunks) ----
#pragma unroll 1
    for (int kc = 0; kc < 8; kc++) {
        if (kc < 7) {
            ldBb_async(g_w4b + (kc + 1) * 10240, bufu[(kc + 1) & 1], t);
            CP_COMMIT();
        }
        uint32_t bbase = bufu[kc & 1];
#pragma unroll
        for (int s = 0; s < 2; s++) {
            uint32_t a[2][4];
            ldsm4(a[0][0], a[0][1], a[0][2], a[0][3], aA[0] + (uint32_t)((kc * 16 + s * 8) * 4));
            ldsm4(a[1][0], a[1][1], a[1][2], a[1][3], aA[1] + (uint32_t)((kc * 16 + s * 8) * 4));
            uint32_t b[8][2];
#pragma unroll
            for (int nt2 = 0; nt2 < 4; nt2++)
                ldsm4(b[2 * nt2][0], b[2 * nt2][1], b[2 * nt2 + 1][0], b[2 * nt2 + 1][1],
                      bbase + bBrel[nt2] + (uint32_t)(s * 32));
#pragma unroll
            for (int nt = 0; nt < 8; nt++)
#pragma unroll
                for (int mt = 0; mt < 2; mt++)
                    mma_bf16(acc[mt][nt], a[mt][0], a[mt][1], a[mt][2], a[mt][3],
                             b[nt][0], b[nt][1]);
        }
        if (kc < 7) {
            CP_WAIT0();
            __syncthreads();
        }
    }

    // epilogue2: pf5 = relu(acc + b4) -> atomicMax scatter into g_vox2
#pragma unroll
    for (int mt = 0; mt < 2; mt++) {
        int lr = wm * 32 + mt * 16 + g;
        int pt0 = row0 + lr, pt1 = pt0 + 8;
        int vr0 = svx[lr], vr1 = svx[lr + 8];
        bool ok0 = pt0 < n, ok1 = pt1 < n;
        float* d0 = g_vox2 + (size_t)vr0 * 256;
        float* d1 = g_vox2 + (size_t)vr1 * 256;
#pragma unroll
        for (int nt = 0; nt < 8; nt++) {
            int c = wn * 64 + nt * 8 + 2 * t4;
            float bc0 = __ldg(b4 + c), bc1 = __ldg(b4 + c + 1);
            if (ok0) {
                amax_pos(d0 + c,     acc[mt][nt][0] + bc0);
                amax_pos(d0 + c + 1, acc[mt][nt][1] + bc1);
            }
            if (ok1) {
                amax_pos(d1 + c,     acc[mt][nt][2] + bc0);
                amax_pos(d1 + c + 1, acc[mt][nt][3] + bc1);
            }
        }
    }
}

// ---------------------------------------------------------------------------
extern "C" void kernel_launch(void* const* d_in, const int* in_sizes, int n_in,
                              void* d_out, int out_size)
{
    const float* inp  = (const float*)d_in[0];
    const int*   vidx = (const int*)d_in[1];
    int base = (n_in >= 23) ? 3 : 2;
    const float* w1x = (const float*)d_in[base + 0];
    const float* b1x = (const float*)d_in[base + 1];
    const float* w2x = (const float*)d_in[base + 2];
    const float* b2x = (const float*)d_in[base + 3];
    const float* w1r = (const float*)d_in[base + 4];
    const float* b1r = (const float*)d_in[base + 5];
    const float* w2r = (const float*)d_in[base + 6];
    const float* b2r = (const float*)d_in[base + 7];
    const float* wax = (const float*)d_in[base + 8];
    const float* bax = (const float*)d_in[base + 9];
    const float* war = (const float*)d_in[base + 10];
    const float* bar = (const float*)d_in[base + 11];
    const float* wv1 = (const float*)d_in[base + 12];
    const float* bv1 = (const float*)d_in[base + 13];
    const float* w3  = (const float*)d_in[base + 14];
    const float* b3  = (const float*)d_in[base + 15];
    const float* w4  = (const float*)d_in[base + 16];
    const float* b4  = (const float*)d_in[base + 17];
    const float* wv2 = (const float*)d_in[base + 18];
    const float* bv2 = (const float*)d_in[base + 19];

    int n = in_sizes[0] / 6;
    int V = out_size / 256;

    const int GO_SMEM = (64 * 132 + 2 * 5120 + 64) * 4;

    auto kOut = gemm_out_bf16<8, 8>;

    cudaFuncSetAttribute(stage_a_mma, cudaFuncAttributeMaxDynamicSharedMemorySize, SAM_SMEM);
    cudaFuncSetAttribute(stage_c_bf16, cudaFuncAttributeMaxDynamicSharedMemorySize, SC4_SMEM);
    cudaFuncSetAttribute(fused_vox, cudaFuncAttributeMaxDynamicSharedMemorySize, FV_SMEM);
    cudaFuncSetAttribute(kOut, cudaFuncAttributeMaxDynamicSharedMemorySize, GO_SMEM);

    float *p_vox2;
    __nv_bfloat16 *p_wvb;
    cudaGetSymbolAddress((void**)&p_vox2, g_vox2);
    cudaGetSymbolAddress((void**)&p_wvb, g_wvb);

    // Fork: weight prep + vox2 zeroing on a side stream, overlapped with
    // stage_a. kernel_launch only runs pre-capture (graph replays don't call
    // it), so per-call stream/event creation is bounded.
    cudaStream_t s2;
    cudaStreamCreate(&s2);
    cudaEvent_t ev1, ev2;
    cudaEventCreateWithFlags(&ev1, cudaEventDisableTiming);
    cudaEventCreateWithFlags(&ev2, cudaEventDisableTiming);

    zero_vox<<<1480, 256>>>(V * 128);                 // needed before stage_a
    cudaEventRecord(ev1, 0);
    cudaStreamWaitEvent(s2, ev1, 0);
    side_init<<<1480, 256, 0, s2>>>(w3, w4, wv2, wv1, V * 256);
    cudaEventRecord(ev2, s2);

    stage_a_mma<<<(n + 127) / 128, SAM_THREADS, SAM_SMEM>>>(
        inp, vidx, n, w1x, b1x, w2x, b2x, w1r, b1r, w2r, b2r, wax, bax, war, bar);

    cudaStreamWaitEvent(0, ev2, 0);                   // join before fused_vox

    fused_vox<<<(V + 63) / 64, 256, FV_SMEM>>>(bv1, V);

    stage_c_bf16<<<(n + 63) / 64, 256, SC4_SMEM>>>(vidx, n, b3, b4);

    kOut<<<(V + 63) / 64, 256, GO_SMEM>>>(p_vox2, p_wvb, bv2, (float*)d_out, V);
}